// round 1
// baseline (speedup 1.0000x reference)
#include <cuda_runtime.h>
#include <math.h>

#define VV 16
#define BB 64
#define TT 256
#define HH 128
#define GG 384      // 3*HH
#define FCN 256
#define CC 10
#define ROWS 8      // batch rows per CTA
#define PITCH 132   // HH + 4 pad -> conflict-free LDS.128

// scratch for concat[b][v] between the two kernels (no device allocs allowed)
__device__ float g_concat[BB * VV];

__device__ __forceinline__ float sigmoidf_(float x) {
    return 1.0f / (1.0f + __expf(-x));
}

__global__ __launch_bounds__(256, 1)
void gru_kernel(const float* __restrict__ x,   const float* __restrict__ Wih,
                const float* __restrict__ Whh, const float* __restrict__ bih,
                const float* __restrict__ bhh, const float* __restrict__ Wp,
                const float* __restrict__ bp)
{
    extern __shared__ float smem[];
    float* sW = smem;                       // GG * PITCH        (202,752 B)
    float* sH = smem + GG * PITCH;          // 2 * ROWS * HH     (8,192 B)
    float* sX = sH + 2 * ROWS * HH;         // ROWS * TT         (8,192 B)

    const int tid = threadIdx.x;
    const int v  = blockIdx.x >> 3;          // 16 variables
    const int b0 = (blockIdx.x & 7) * ROWS;  // 8 batch-groups of 8

    // ---- stage Whh[v] into padded smem (coalesced gmem read, conflict-free smem write)
    const float* Whh_v = Whh + (size_t)v * GG * HH;
    for (int idx = tid; idx < GG * HH; idx += 256) {
        int g = idx >> 7, k = idx & 127;
        sW[g * PITCH + k] = Whh_v[idx];
    }
    // ---- stage x slice [ROWS][TT]
    const float* x_v = x + (size_t)(v * BB + b0) * TT;
    for (int idx = tid; idx < ROWS * TT; idx += 256) sX[idx] = x_v[idx];
    // ---- zero both h buffers
    for (int idx = tid; idx < 2 * ROWS * HH; idx += 256) sH[idx] = 0.0f;

    const int j  = tid & 127;   // hidden index (gate column)
    const int u  = tid >> 7;    // row-half: rows [4u, 4u+4)
    const int r0 = u * 4;

    // per-thread gate constants (gi folded per step: gi = x*Wih + bih)
    const float wih_r = Wih[v * GG + j];
    const float wih_z = Wih[v * GG + HH + j];
    const float wih_n = Wih[v * GG + 2 * HH + j];
    const float bi_r = bih[v * GG + j],     bi_z = bih[v * GG + HH + j],     bi_n = bih[v * GG + 2 * HH + j];
    const float bh_r = bhh[v * GG + j],     bh_z = bhh[v * GG + HH + j],     bh_n = bhh[v * GG + 2 * HH + j];

    const float4* w_r = (const float4*)(sW + j * PITCH);
    const float4* w_z = (const float4*)(sW + (HH + j) * PITCH);
    const float4* w_n = (const float4*)(sW + (2 * HH + j) * PITCH);

    __syncthreads();

    int cur = 0;
    for (int t = 0; t < TT; t++) {
        const float4* hc = (const float4*)(sH + cur * ROWS * HH + r0 * HH);

        float ar[4] = {0.f, 0.f, 0.f, 0.f};
        float az[4] = {0.f, 0.f, 0.f, 0.f};
        float an[4] = {0.f, 0.f, 0.f, 0.f};

        #pragma unroll 4
        for (int k4 = 0; k4 < HH / 4; k4++) {
            float4 wr = w_r[k4];
            float4 wz = w_z[k4];
            float4 wn = w_n[k4];
            #pragma unroll
            for (int r = 0; r < 4; r++) {
                float4 hv = hc[r * (HH / 4) + k4];   // warp-broadcast
                ar[r] = fmaf(wr.x, hv.x, ar[r]); ar[r] = fmaf(wr.y, hv.y, ar[r]);
                ar[r] = fmaf(wr.z, hv.z, ar[r]); ar[r] = fmaf(wr.w, hv.w, ar[r]);
                az[r] = fmaf(wz.x, hv.x, az[r]); az[r] = fmaf(wz.y, hv.y, az[r]);
                az[r] = fmaf(wz.z, hv.z, az[r]); az[r] = fmaf(wz.w, hv.w, az[r]);
                an[r] = fmaf(wn.x, hv.x, an[r]); an[r] = fmaf(wn.y, hv.y, an[r]);
                an[r] = fmaf(wn.z, hv.z, an[r]); an[r] = fmaf(wn.w, hv.w, an[r]);
            }
        }

        const float* hcs = sH + cur * ROWS * HH + r0 * HH;
        float* hns = sH + (cur ^ 1) * ROWS * HH + r0 * HH;
        #pragma unroll
        for (int r = 0; r < 4; r++) {
            float xv = sX[(r0 + r) * TT + t];
            float rg = sigmoidf_(fmaf(xv, wih_r, bi_r) + ar[r] + bh_r);
            float zg = sigmoidf_(fmaf(xv, wih_z, bi_z) + az[r] + bh_z);
            float ng = tanhf(fmaf(xv, wih_n, bi_n) + rg * (an[r] + bh_n));
            float hp = hcs[r * HH + j];
            // (1-z)*n + z*h  ==  n + z*(h-n)
            hns[r * HH + j] = fmaf(zg, hp - ng, ng);
        }
        __syncthreads();
        cur ^= 1;
    }

    // ---- concat[b][v] = sum_j h_last * Wp[v][j] + bp[v]   (one warp per row)
    const int w = tid >> 5, lane = tid & 31;
    const float* hl = sH + cur * ROWS * HH + w * HH;
    const float* Wp_v = Wp + v * HH;
    float s = 0.0f;
    #pragma unroll
    for (int q = 0; q < 4; q++) {
        int jj = lane + 32 * q;
        s = fmaf(hl[jj], Wp_v[jj], s);
    }
    #pragma unroll
    for (int off = 16; off; off >>= 1) s += __shfl_xor_sync(0xffffffffu, s, off);
    if (lane == 0) g_concat[(b0 + w) * VV + v] = s + bp[v];
}

__global__ __launch_bounds__(256, 1)
void fc_kernel(const float* __restrict__ W1, const float* __restrict__ b1,
               const float* __restrict__ W2, const float* __restrict__ b2,
               float* __restrict__ out)
{
    extern __shared__ float smem[];
    float* sC = smem;            // BB*VV
    float* sF = smem + BB * VV;  // BB*FCN

    const int tid = threadIdx.x;
    for (int idx = tid; idx < BB * VV; idx += 256) sC[idx] = g_concat[idx];
    __syncthreads();

    // hfc[b][f] = relu(sum_v concat[b][v] * W1[f][v] + b1[f]);  f = tid
    {
        float w1[VV];
        #pragma unroll
        for (int vv = 0; vv < VV; vv++) w1[vv] = W1[tid * VV + vv];
        const float bb1 = b1[tid];
        for (int b = 0; b < BB; b++) {
            float a = bb1;
            #pragma unroll
            for (int vv = 0; vv < VV; vv++) a = fmaf(sC[b * VV + vv], w1[vv], a);
            sF[b * FCN + tid] = fmaxf(a, 0.0f);
        }
    }
    __syncthreads();

    // out[b][c] = sum_f hfc[b][f] * W2[c][f] + b2[c]
    for (int idx = tid; idx < BB * CC; idx += 256) {
        int b = idx / CC, c = idx % CC;
        float a = b2[c];
        #pragma unroll 8
        for (int f = 0; f < FCN; f++) a = fmaf(sF[b * FCN + f], W2[c * FCN + f], a);
        out[idx] = a;
    }
}

extern "C" void kernel_launch(void* const* d_in, const int* in_sizes, int n_in,
                              void* d_out, int out_size)
{
    const float* x   = (const float*)d_in[0];
    const float* Wih = (const float*)d_in[1];
    const float* Whh = (const float*)d_in[2];
    const float* bih = (const float*)d_in[3];
    const float* bhh = (const float*)d_in[4];
    const float* Wp  = (const float*)d_in[5];
    const float* bp  = (const float*)d_in[6];
    const float* W1  = (const float*)d_in[7];
    const float* b1  = (const float*)d_in[8];
    const float* W2  = (const float*)d_in[9];
    const float* b2  = (const float*)d_in[10];
    float* out = (float*)d_out;

    const int smem1 = (GG * PITCH + 2 * ROWS * HH + ROWS * TT) * (int)sizeof(float); // 219,136 B
    const int smem2 = (BB * VV + BB * FCN) * (int)sizeof(float);                      // 69,632 B
    cudaFuncSetAttribute(gru_kernel, cudaFuncAttributeMaxDynamicSharedMemorySize, smem1);
    cudaFuncSetAttribute(fc_kernel,  cudaFuncAttributeMaxDynamicSharedMemorySize, smem2);

    gru_kernel<<<VV * (BB / ROWS), 256, smem1>>>(x, Wih, Whh, bih, bhh, Wp, bp);
    fc_kernel<<<1, 256, smem2>>>(W1, b1, W2, b2, out);
}

// round 2
// speedup vs baseline: 1.0015x; 1.0015x over previous
#include <cuda_runtime.h>
#include <math.h>

#define VV 16
#define BB 64
#define TT 256
#define HH 128
#define GG 384      // 3*HH
#define FCN 256
#define CC 10
#define ROWS 8      // batch rows per CTA
#define PITCH 132   // HH + 4 pad -> conflict-free LDS.128

// scratch for concat[b][v] between the two kernels (no device allocs allowed)
__device__ float g_concat[BB * VV];

__device__ __forceinline__ float sigmoidf_(float x) {
    return 1.0f / (1.0f + __expf(-x));
}

// packed fp32x2 FMA: acc = a*b + acc (elementwise on 2 packed floats)
__device__ __forceinline__ void ffma2(unsigned long long& acc,
                                      unsigned long long a,
                                      unsigned long long b) {
    asm("fma.rn.f32x2 %0, %1, %2, %0;" : "+l"(acc) : "l"(a), "l"(b));
}

__device__ __forceinline__ float pairsum(unsigned long long a) {
    float lo, hi;
    asm("mov.b64 {%0, %1}, %2;" : "=f"(lo), "=f"(hi) : "l"(a));
    return lo + hi;
}

__global__ __launch_bounds__(256, 1)
void gru_kernel(const float* __restrict__ x,   const float* __restrict__ Wih,
                const float* __restrict__ Whh, const float* __restrict__ bih,
                const float* __restrict__ bhh, const float* __restrict__ Wp,
                const float* __restrict__ bp)
{
    extern __shared__ float smem[];
    float* sW = smem;                       // GG * PITCH        (202,752 B)
    float* sH = smem + GG * PITCH;          // 2 * ROWS * HH     (8,192 B)
    float* sX = sH + 2 * ROWS * HH;         // ROWS * TT         (8,192 B)

    const int tid = threadIdx.x;
    const int v  = blockIdx.x >> 3;          // 16 variables
    const int b0 = (blockIdx.x & 7) * ROWS;  // 8 batch-groups of 8

    // ---- stage Whh[v] into padded smem
    const float* Whh_v = Whh + (size_t)v * GG * HH;
    for (int idx = tid; idx < GG * HH; idx += 256) {
        int g = idx >> 7, k = idx & 127;
        sW[g * PITCH + k] = Whh_v[idx];
    }
    // ---- stage x slice [ROWS][TT]
    const float* x_v = x + (size_t)(v * BB + b0) * TT;
    for (int idx = tid; idx < ROWS * TT; idx += 256) sX[idx] = x_v[idx];
    // ---- zero both h buffers
    for (int idx = tid; idx < 2 * ROWS * HH; idx += 256) sH[idx] = 0.0f;

    const int j  = tid & 127;   // hidden index (gate column)
    const int u  = tid >> 7;    // row-half: rows [4u, 4u+4)
    const int r0 = u * 4;

    // per-thread gate constants (gi folded per step: gi = x*Wih + bih)
    const float wih_r = Wih[v * GG + j];
    const float wih_z = Wih[v * GG + HH + j];
    const float wih_n = Wih[v * GG + 2 * HH + j];
    const float bi_r = bih[v * GG + j],     bi_z = bih[v * GG + HH + j],     bi_n = bih[v * GG + 2 * HH + j];
    const float bh_r = bhh[v * GG + j],     bh_z = bhh[v * GG + HH + j],     bh_n = bhh[v * GG + 2 * HH + j];

    // 16B views: each ulonglong2 element = 4 floats = 2 packed f32x2 operands
    const ulonglong2* w_r = (const ulonglong2*)(sW + j * PITCH);
    const ulonglong2* w_z = (const ulonglong2*)(sW + (HH + j) * PITCH);
    const ulonglong2* w_n = (const ulonglong2*)(sW + (2 * HH + j) * PITCH);

    __syncthreads();

    int cur = 0;
    for (int t = 0; t < TT; t++) {
        const ulonglong2* hc = (const ulonglong2*)(sH + cur * ROWS * HH + r0 * HH);

        unsigned long long ar2[4] = {0ull, 0ull, 0ull, 0ull};
        unsigned long long az2[4] = {0ull, 0ull, 0ull, 0ull};
        unsigned long long an2[4] = {0ull, 0ull, 0ull, 0ull};

        #pragma unroll 4
        for (int k4 = 0; k4 < HH / 4; k4++) {
            ulonglong2 wr = w_r[k4];
            ulonglong2 wz = w_z[k4];
            ulonglong2 wn = w_n[k4];
            #pragma unroll
            for (int r = 0; r < 4; r++) {
                ulonglong2 hv = hc[r * (HH / 4) + k4];   // warp-broadcast
                ffma2(ar2[r], wr.x, hv.x); ffma2(ar2[r], wr.y, hv.y);
                ffma2(az2[r], wz.x, hv.x); ffma2(az2[r], wz.y, hv.y);
                ffma2(an2[r], wn.x, hv.x); ffma2(an2[r], wn.y, hv.y);
            }
        }

        const float* hcs = sH + cur * ROWS * HH + r0 * HH;
        float* hns = sH + (cur ^ 1) * ROWS * HH + r0 * HH;
        #pragma unroll
        for (int r = 0; r < 4; r++) {
            float xv = sX[(r0 + r) * TT + t];
            float rg = sigmoidf_(fmaf(xv, wih_r, bi_r) + pairsum(ar2[r]) + bh_r);
            float zg = sigmoidf_(fmaf(xv, wih_z, bi_z) + pairsum(az2[r]) + bh_z);
            float ng = tanhf(fmaf(xv, wih_n, bi_n) + rg * (pairsum(an2[r]) + bh_n));
            float hp = hcs[r * HH + j];
            // (1-z)*n + z*h  ==  n + z*(h-n)
            hns[r * HH + j] = fmaf(zg, hp - ng, ng);
        }
        __syncthreads();
        cur ^= 1;
    }

    // ---- concat[b][v] = sum_j h_last * Wp[v][j] + bp[v]   (one warp per row)
    const int w = tid >> 5, lane = tid & 31;
    const float* hl = sH + cur * ROWS * HH + w * HH;
    const float* Wp_v = Wp + v * HH;
    float s = 0.0f;
    #pragma unroll
    for (int q = 0; q < 4; q++) {
        int jj = lane + 32 * q;
        s = fmaf(hl[jj], Wp_v[jj], s);
    }
    #pragma unroll
    for (int off = 16; off; off >>= 1) s += __shfl_xor_sync(0xffffffffu, s, off);
    if (lane == 0) g_concat[(b0 + w) * VV + v] = s + bp[v];
}

// one CTA per batch row; warp-per-class output reduction
__global__ __launch_bounds__(256, 1)
void fc_kernel(const float* __restrict__ W1, const float* __restrict__ b1,
               const float* __restrict__ W2, const float* __restrict__ b2,
               float* __restrict__ out)
{
    __shared__ float sC[VV];
    __shared__ float sF[FCN];

    const int b = blockIdx.x;
    const int tid = threadIdx.x;

    if (tid < VV) sC[tid] = g_concat[b * VV + tid];
    __syncthreads();

    // hfc[f] = relu(sum_v concat[v] * W1[f][v] + b1[f]);  f = tid
    {
        float a = b1[tid];
        const float* w1 = W1 + tid * VV;
        #pragma unroll
        for (int vv = 0; vv < VV; vv++) a = fmaf(sC[vv], w1[vv], a);
        sF[tid] = fmaxf(a, 0.0f);
    }
    __syncthreads();

    // out[b][c] = sum_f hfc[f] * W2[c][f] + b2[c]   (one warp per class)
    const int wid = tid >> 5, lane = tid & 31;
    for (int c = wid; c < CC; c += 8) {
        const float* w2 = W2 + c * FCN;
        float a = 0.0f;
        #pragma unroll
        for (int q = 0; q < FCN / 32; q++) {
            int f = lane + 32 * q;
            a = fmaf(sF[f], w2[f], a);
        }
        #pragma unroll
        for (int off = 16; off; off >>= 1) a += __shfl_xor_sync(0xffffffffu, a, off);
        if (lane == 0) out[b * CC + c] = a + b2[c];
    }
}

extern "C" void kernel_launch(void* const* d_in, const int* in_sizes, int n_in,
                              void* d_out, int out_size)
{
    const float* x   = (const float*)d_in[0];
    const float* Wih = (const float*)d_in[1];
    const float* Whh = (const float*)d_in[2];
    const float* bih = (const float*)d_in[3];
    const float* bhh = (const float*)d_in[4];
    const float* Wp  = (const float*)d_in[5];
    const float* bp  = (const float*)d_in[6];
    const float* W1  = (const float*)d_in[7];
    const float* b1  = (const float*)d_in[8];
    const float* W2  = (const float*)d_in[9];
    const float* b2  = (const float*)d_in[10];
    float* out = (float*)d_out;

    const int smem1 = (GG * PITCH + 2 * ROWS * HH + ROWS * TT) * (int)sizeof(float); // 219,136 B
    cudaFuncSetAttribute(gru_kernel, cudaFuncAttributeMaxDynamicSharedMemorySize, smem1);

    gru_kernel<<<VV * (BB / ROWS), 256, smem1>>>(x, Wih, Whh, bih, bhh, Wp, bp);
    fc_kernel<<<BB, 256>>>(W1, b1, W2, b2, out);
}

// round 3
// speedup vs baseline: 1.0107x; 1.0092x over previous
#include <cuda_runtime.h>
#include <math.h>

#define VV 16
#define BB 64
#define TT 256
#define HH 128
#define GG 384      // 3*HH
#define FCN 256
#define CC 10
#define ROWS 8      // batch rows per CTA
#define NTHR 384    // one thread per gate-row g

typedef unsigned long long ull;

// scratch for concat[b][v] between the two kernels (no device allocs allowed)
__device__ float g_concat[BB * VV];

__device__ __forceinline__ float sigmoidf_(float x) {
    return 1.0f / (1.0f + __expf(-x));
}

// packed fp32x2 FMA: acc = a*b + acc (elementwise on 2 packed floats)
__device__ __forceinline__ void ffma2(ull& acc, ull a, ull b) {
    asm("fma.rn.f32x2 %0, %1, %2, %0;" : "+l"(acc) : "l"(a), "l"(b));
}

__device__ __forceinline__ float pairsum(ull a) {
    float lo, hi;
    asm("mov.b64 {%0, %1}, %2;" : "=f"(lo), "=f"(hi) : "l"(a));
    return lo + hi;
}

__device__ __forceinline__ ull pack_lo(float lo) {
    ull r;
    asm("mov.b64 %0, {%1, %2};" : "=l"(r) : "f"(lo), "f"(0.0f));
    return r;
}

__global__ __launch_bounds__(NTHR, 1)
void gru_kernel(const float* __restrict__ x,   const float* __restrict__ Wih,
                const float* __restrict__ Whh, const float* __restrict__ bih,
                const float* __restrict__ bhh, const float* __restrict__ Wp,
                const float* __restrict__ bp)
{
    __shared__ __align__(16) float sH[2][ROWS * HH];   // double-buffered hidden state
    __shared__ float sGH[ROWS][GG];                    // gh exchange: [r][g], conflict-free
    __shared__ __align__(16) float sX[ROWS][TT];       // input slice
    __shared__ float sWihA[GG];                        // Wih[v][g] (input weight, scalar per gate-row)
    __shared__ float sBihA[GG];                        // bih[v][g]

    const int tid = threadIdx.x;
    const int v  = blockIdx.x >> 3;          // 16 variables
    const int b0 = (blockIdx.x & 7) * ROWS;  // 8 batch-groups of 8
    const int g  = tid;                      // this thread's gate-row (0..383)

    // ---- stage per-gate-row input constants
    sWihA[g] = Wih[v * GG + g];
    sBihA[g] = bih[v * GG + g];
    const float bh_g = bhh[v * GG + g];      // folded into accumulator init

    // ---- stage x slice [ROWS][TT]
    const float* x_v = x + (size_t)(v * BB + b0) * TT;
    for (int idx = tid; idx < ROWS * TT; idx += NTHR) ((float*)sX)[idx] = x_v[idx];
    // ---- zero h buffer 0
    for (int idx = tid; idx < ROWS * HH; idx += NTHR) sH[0][idx] = 0.0f;

    // ---- load this thread's weight row into registers (f32x2-packed, 64 ull = 128 regs)
    ull wreg[64];
    {
        const ull* wrow = (const ull*)(Whh + ((size_t)v * GG + g) * HH);
        #pragma unroll
        for (int i = 0; i < 64; i++) wreg[i] = wrow[i];
    }

    const int j     = tid & 127;   // hidden index for phase 2
    const int third = tid >> 7;    // 0,1,2 -> gate bank / row partition for phase 2

    __syncthreads();

    int cur = 0;
    for (int t = 0; t < TT; t++) {
        // ======== phase 1: gh[g][r] = Whh[g,:] . h[r,:]  (+ bhh[g]) ========
        const float* sHc = sH[cur];

        ull acc[ROWS];
        #pragma unroll
        for (int r = 0; r < ROWS; r++) acc[r] = pack_lo(bh_g);

        #pragma unroll
        for (int k4 = 0; k4 < HH / 4; k4++) {
            const ull w0 = wreg[2 * k4];
            const ull w1 = wreg[2 * k4 + 1];
            #pragma unroll
            for (int r = 0; r < ROWS; r++) {
                ulonglong2 hv = *(const ulonglong2*)(sHc + r * HH + k4 * 4);  // broadcast
                ffma2(acc[r], w0, hv.x);
                ffma2(acc[r], w1, hv.y);
            }
        }
        #pragma unroll
        for (int r = 0; r < ROWS; r++) sGH[r][g] = pairsum(acc[r]);

        __syncthreads();

        // ======== phase 2: GRU update, rows partitioned by 'third' ========
        float* sHn = sH[cur ^ 1];
        for (int r = third; r < ROWS; r += 3) {
            float gr = sGH[r][j];
            float gz = sGH[r][j + HH];
            float gn = sGH[r][j + 2 * HH];
            float xv = sX[r][t];
            float ir = fmaf(xv, sWihA[j],          sBihA[j]);
            float iz = fmaf(xv, sWihA[j + HH],     sBihA[j + HH]);
            float in_ = fmaf(xv, sWihA[j + 2*HH],  sBihA[j + 2*HH]);
            float rg = sigmoidf_(ir + gr);
            float zg = sigmoidf_(iz + gz);
            float ng = tanhf(in_ + rg * gn);
            float hp = sHc[r * HH + j];
            sHn[r * HH + j] = fmaf(zg, hp - ng, ng);   // (1-z)*n + z*h
        }
        __syncthreads();
        cur ^= 1;
    }

    // ---- concat[b][v] = sum_j h_last[r][j] * Wp[v][j] + bp[v]  (one warp per row)
    if (tid < ROWS * 32) {
        const int w = tid >> 5, lane = tid & 31;
        const float* hl = sH[cur] + w * HH;
        const float* Wp_v = Wp + v * HH;
        float s = 0.0f;
        #pragma unroll
        for (int q = 0; q < 4; q++) {
            int jj = lane + 32 * q;
            s = fmaf(hl[jj], Wp_v[jj], s);
        }
        #pragma unroll
        for (int off = 16; off; off >>= 1) s += __shfl_xor_sync(0xffffffffu, s, off);
        if (lane == 0) g_concat[(b0 + w) * VV + v] = s + bp[v];
    }
}

// one CTA per batch row; warp-per-class output reduction
__global__ __launch_bounds__(256, 1)
void fc_kernel(const float* __restrict__ W1, const float* __restrict__ b1,
               const float* __restrict__ W2, const float* __restrict__ b2,
               float* __restrict__ out)
{
    __shared__ float sC[VV];
    __shared__ float sF[FCN];

    const int b = blockIdx.x;
    const int tid = threadIdx.x;

    if (tid < VV) sC[tid] = g_concat[b * VV + tid];
    __syncthreads();

    {
        float a = b1[tid];
        const float* w1 = W1 + tid * VV;
        #pragma unroll
        for (int vv = 0; vv < VV; vv++) a = fmaf(sC[vv], w1[vv], a);
        sF[tid] = fmaxf(a, 0.0f);
    }
    __syncthreads();

    const int wid = tid >> 5, lane = tid & 31;
    for (int c = wid; c < CC; c += 8) {
        const float* w2 = W2 + c * FCN;
        float a = 0.0f;
        #pragma unroll
        for (int q = 0; q < FCN / 32; q++) {
            int f = lane + 32 * q;
            a = fmaf(sF[f], w2[f], a);
        }
        #pragma unroll
        for (int off = 16; off; off >>= 1) a += __shfl_xor_sync(0xffffffffu, a, off);
        if (lane == 0) out[b * CC + c] = a + b2[c];
    }
}

extern "C" void kernel_launch(void* const* d_in, const int* in_sizes, int n_in,
                              void* d_out, int out_size)
{
    const float* x   = (const float*)d_in[0];
    const float* Wih = (const float*)d_in[1];
    const float* Whh = (const float*)d_in[2];
    const float* bih = (const float*)d_in[3];
    const float* bhh = (const float*)d_in[4];
    const float* Wp  = (const float*)d_in[5];
    const float* bp  = (const float*)d_in[6];
    const float* W1  = (const float*)d_in[7];
    const float* b1  = (const float*)d_in[8];
    const float* W2  = (const float*)d_in[9];
    const float* b2  = (const float*)d_in[10];
    float* out = (float*)d_out;

    gru_kernel<<<VV * (BB / ROWS), NTHR>>>(x, Wih, Whh, bih, bhh, Wp, bp);
    fc_kernel<<<BB, 256>>>(W1, b1, W2, b2, out);
}

// round 5
// speedup vs baseline: 1.8748x; 1.8550x over previous
#include <cuda_runtime.h>
#include <cuda_bf16.h>
#include <math.h>

#define VV 16
#define BB 64
#define TT 256
#define HH 128
#define GG 384
#define FCN 256
#define CC 10
#define NB 8            // batch rows per CTA = MMA N
#define NTHR 384        // 12 warps

// ---- smem byte offsets ----
#define OFF_WHI 0                        // W_hi bf16 [384][128], swizzled 256B rows
#define OFF_WLO (OFF_WHI + GG*256)       // 98304
#define OFF_HHI (OFF_WLO + GG*256)       // 196608: h_hi bf16 [8][128]
#define OFF_HLO (OFF_HHI + NB*256)       // 198656: h_lo
#define OFF_GH  (OFF_HLO + NB*256)       // 200704: gh f32 [384][8]
#define OFF_X   (OFF_GH + GG*NB*4)       // 212992: x f32 [8][256] (reused as hfin)
#define SMEM_TOT (OFF_X + NB*TT*4)       // 221184

typedef unsigned int u32;

__device__ float g_concat[BB * VV];

// XOR-swizzled byte offset within a [rows][128] bf16 tile (256B rows, 16B chunks)
__device__ __forceinline__ int swz(int r, int k) {
    return r * 256 + ((((k >> 3) ^ (r & 7)) & 15) << 4) + ((k & 7) << 1);
}

__device__ __forceinline__ u32 smem_u32(const void* p) {
    u32 a;
    asm("{ .reg .u64 t; cvta.to.shared.u64 t, %1; cvt.u32.u64 %0, t; }" : "=r"(a) : "l"(p));
    return a;
}

__device__ __forceinline__ void ldsm4(u32& a0, u32& a1, u32& a2, u32& a3, u32 addr) {
    asm volatile("ldmatrix.sync.aligned.m8n8.x4.shared.b16 {%0,%1,%2,%3}, [%4];"
                 : "=r"(a0), "=r"(a1), "=r"(a2), "=r"(a3) : "r"(addr));
}
__device__ __forceinline__ void ldsm2(u32& b0, u32& b1, u32 addr) {
    asm volatile("ldmatrix.sync.aligned.m8n8.x2.shared.b16 {%0,%1}, [%2];"
                 : "=r"(b0), "=r"(b1) : "r"(addr));
}
__device__ __forceinline__ void mma16816(float* d, u32 a0, u32 a1, u32 a2, u32 a3,
                                         u32 b0, u32 b1) {
    asm volatile("mma.sync.aligned.m16n8k16.row.col.f32.bf16.bf16.f32 "
                 "{%0,%1,%2,%3}, {%4,%5,%6,%7}, {%8,%9}, {%0,%1,%2,%3};"
                 : "+f"(d[0]), "+f"(d[1]), "+f"(d[2]), "+f"(d[3])
                 : "r"(a0), "r"(a1), "r"(a2), "r"(a3), "r"(b0), "r"(b1));
}

__device__ __forceinline__ float sigmoidf_(float x) {
    return 1.0f / (1.0f + __expf(-x));
}

__global__ __launch_bounds__(NTHR, 1)
void gru_kernel(const float* __restrict__ x,   const float* __restrict__ Wih,
                const float* __restrict__ Whh, const float* __restrict__ bih,
                const float* __restrict__ bhh, const float* __restrict__ Wp,
                const float* __restrict__ bp)
{
    extern __shared__ char sm[];
    const u32 smb = smem_u32(sm);
    const int tid = threadIdx.x;
    const int v  = blockIdx.x >> 3;          // 16 variables
    const int b0 = (blockIdx.x & 7) * NB;    // 8 batch-groups of 8

    // ---- stage Whh[v] as bf16 hi/lo into swizzled tiles ----
    const float* Whh_v = Whh + (size_t)v * GG * HH;
    for (int idx = tid; idx < GG * HH; idx += NTHR) {
        int g = idx >> 7, k = idx & 127;
        float wv = Whh_v[idx];
        __nv_bfloat16 hi = __float2bfloat16(wv);
        __nv_bfloat16 lo = __float2bfloat16(wv - __bfloat162float(hi));
        int o = swz(g, k);
        *(__nv_bfloat16*)(sm + OFF_WHI + o) = hi;
        *(__nv_bfloat16*)(sm + OFF_WLO + o) = lo;
    }
    // ---- zero h tiles (h0 = 0; bf16 zero = 0x0000) ----
    for (int idx = tid; idx < (2 * NB * 256) / 4; idx += NTHR)
        ((u32*)(sm + OFF_HHI))[idx] = 0u;
    // ---- stage x slice ----
    float* sXf = (float*)(sm + OFF_X);
    const float* x_v = x + (size_t)(v * BB + b0) * TT;
    for (int idx = tid; idx < NB * TT; idx += NTHR) sXf[idx] = x_v[idx];

    // ---- phase-2 per-thread constants ----
    const int j   = tid & 127;
    const int sub = tid >> 7;      // 0..2; phase-2 active iff tid<256
    float wr = 0, wz = 0, wn = 0, bias_r = 0, bias_z = 0, bi_n = 0, bh_n = 0;
    if (tid < 256) {
        wr = Wih[v * GG + j]; wz = Wih[v * GG + 128 + j]; wn = Wih[v * GG + 256 + j];
        bias_r = bih[v * GG + j]       + bhh[v * GG + j];
        bias_z = bih[v * GG + 128 + j] + bhh[v * GG + 128 + j];
        bi_n   = bih[v * GG + 256 + j];
        bh_n   = bhh[v * GG + 256 + j];
    }

    // ---- phase-1 lane geometry ----
    const int w = tid >> 5, L = tid & 31;
    const int rowl  = ((L >> 3) & 1) * 8 + (L & 7);  // A: row within 16-tile
    const int khalf = (L >> 4) & 1;                  // A: k chunk half
    const int xr    = L & 7;                         // A swizzle key
    const int nrow  = L & 7;                         // B: h row (n)
    const int csel  = (L >> 3) & 1;                  // B: chunk select
    const u32 aHi0 = smb + OFF_WHI + (u32)(32 * w + rowl) * 256;
    const u32 aHi1 = aHi0 + 16 * 256;
    const u32 aLo0 = aHi0 + (OFF_WLO - OFF_WHI);
    const u32 aLo1 = aHi1 + (OFF_WLO - OFF_WHI);
    const u32 bHiB = smb + OFF_HHI + (u32)nrow * 256;
    const u32 bLoB = bHiB + NB * 256;
    // gh store geometry
    const int quad = L >> 2, qc = L & 3;

    float hreg[4] = {0.f, 0.f, 0.f, 0.f};

    __syncthreads();

    for (int t = 0; t < TT; t++) {
        // ============ phase 1: gh = [Whh_hi+lo][h_hi+lo] via HMMA ============
        float acc0[4] = {0.f, 0.f, 0.f, 0.f};
        float acc1[4] = {0.f, 0.f, 0.f, 0.f};
        #pragma unroll
        for (int s = 0; s < 8; s++) {
            const u32 ca = (u32)((((2 * s + khalf) ^ xr) & 15) << 4);
            const u32 cb = (u32)((((2 * s + csel) ^ nrow) & 15) << 4);
            u32 ah0, ah1, ah2, ah3, al0, al1, al2, al3;
            u32 ah4, ah5, ah6, ah7, al4, al5, al6, al7;
            u32 bh0, bh1, bl0, bl1;
            ldsm4(ah0, ah1, ah2, ah3, aHi0 + ca);
            ldsm4(ah4, ah5, ah6, ah7, aHi1 + ca);
            ldsm4(al0, al1, al2, al3, aLo0 + ca);
            ldsm4(al4, al5, al6, al7, aLo1 + ca);
            ldsm2(bh0, bh1, bHiB + cb);
            ldsm2(bl0, bl1, bLoB + cb);
            mma16816(acc0, ah0, ah1, ah2, ah3, bh0, bh1);   // Whi * h_hi
            mma16816(acc1, ah4, ah5, ah6, ah7, bh0, bh1);
            mma16816(acc0, ah0, ah1, ah2, ah3, bl0, bl1);   // Whi * h_lo
            mma16816(acc1, ah4, ah5, ah6, ah7, bl0, bl1);
            mma16816(acc0, al0, al1, al2, al3, bh0, bh1);   // Wlo * h_hi
            mma16816(acc1, al4, al5, al6, al7, bh0, bh1);
        }
        // store gh tiles: D[row][col] -> sGH[g][b]
        {
            char* gh = sm + OFF_GH;
            int g00 = 32 * w + quad;
            *(float2*)(gh + (g00)      * 32 + qc * 8) = make_float2(acc0[0], acc0[1]);
            *(float2*)(gh + (g00 + 8)  * 32 + qc * 8) = make_float2(acc0[2], acc0[3]);
            *(float2*)(gh + (g00 + 16) * 32 + qc * 8) = make_float2(acc1[0], acc1[1]);
            *(float2*)(gh + (g00 + 24) * 32 + qc * 8) = make_float2(acc1[2], acc1[3]);
        }
        __syncthreads();

        // ============ phase 2: gates + state update (256 threads) ============
        if (tid < 256) {
            const char* gh = sm + OFF_GH;
            float4 g_r = *(const float4*)(gh + (size_t)j * 32 + sub * 16);
            float4 g_z = *(const float4*)(gh + (size_t)(128 + j) * 32 + sub * 16);
            float4 g_n = *(const float4*)(gh + (size_t)(256 + j) * 32 + sub * 16);
            float ghr[4] = {g_r.x, g_r.y, g_r.z, g_r.w};
            float ghz[4] = {g_z.x, g_z.y, g_z.z, g_z.w};
            float ghn[4] = {g_n.x, g_n.y, g_n.z, g_n.w};
            #pragma unroll
            for (int i = 0; i < 4; i++) {
                int b = 4 * sub + i;
                float xv = sXf[b * TT + t];
                float rg = sigmoidf_(fmaf(xv, wr, bias_r) + ghr[i]);
                float zg = sigmoidf_(fmaf(xv, wz, bias_z) + ghz[i]);
                float ng = tanhf(fmaf(xv, wn, bi_n) + rg * (ghn[i] + bh_n));
                float hn = fmaf(zg, hreg[i] - ng, ng);     // (1-z)*n + z*h
                hreg[i] = hn;
                __nv_bfloat16 hi16 = __float2bfloat16(hn);
                __nv_bfloat16 lo16 = __float2bfloat16(hn - __bfloat162float(hi16));
                int o = swz(b, j);
                *(__nv_bfloat16*)(sm + OFF_HHI + o) = hi16;
                *(__nv_bfloat16*)(sm + OFF_HLO + o) = lo16;
            }
        }
        __syncthreads();
    }

    // ============ epilogue: concat[b][v] ============
    float* hfin = (float*)(sm + OFF_X);   // reuse x region: [8][128] f32
    if (tid < 256) {
        #pragma unroll
        for (int i = 0; i < 4; i++) hfin[(4 * sub + i) * HH + j] = hreg[i];
    }
    __syncthreads();

    if (w < NB) {
        const float* Wp_v = Wp + v * HH;
        float s = 0.0f;
        #pragma unroll
        for (int q = 0; q < 4; q++) {
            int jj = (tid & 31) + 32 * q;
            s = fmaf(hfin[w * HH + jj], Wp_v[jj], s);
        }
        #pragma unroll
        for (int off = 16; off; off >>= 1) s += __shfl_xor_sync(0xffffffffu, s, off);
        if ((tid & 31) == 0) g_concat[(b0 + w) * VV + v] = s + bp[v];
    }
}

// one CTA per batch row; warp-per-class output reduction
__global__ __launch_bounds__(256, 1)
void fc_kernel(const float* __restrict__ W1, const float* __restrict__ b1,
               const float* __restrict__ W2, const float* __restrict__ b2,
               float* __restrict__ out)
{
    __shared__ float sC[VV];
    __shared__ float sF[FCN];

    const int b = blockIdx.x;
    const int tid = threadIdx.x;

    if (tid < VV) sC[tid] = g_concat[b * VV + tid];
    __syncthreads();

    {
        float a = b1[tid];
        const float* w1 = W1 + tid * VV;
        #pragma unroll
        for (int vv = 0; vv < VV; vv++) a = fmaf(sC[vv], w1[vv], a);
        sF[tid] = fmaxf(a, 0.0f);
    }
    __syncthreads();

    const int wid = tid >> 5, lane = tid & 31;
    for (int c = wid; c < CC; c += 8) {
        const float* w2 = W2 + c * FCN;
        float a = 0.0f;
        #pragma unroll
        for (int q = 0; q < FCN / 32; q++) {
            int f = lane + 32 * q;
            a = fmaf(sF[f], w2[f], a);
        }
        #pragma unroll
        for (int off = 16; off; off >>= 1) a += __shfl_xor_sync(0xffffffffu, a, off);
        if (lane == 0) out[b * CC + c] = a + b2[c];
    }
}

extern "C" void kernel_launch(void* const* d_in, const int* in_sizes, int n_in,
                              void* d_out, int out_size)
{
    const float* x   = (const float*)d_in[0];
    const float* Wih = (const float*)d_in[1];
    const float* Whh = (const float*)d_in[2];
    const float* bih = (const float*)d_in[3];
    const float* bhh = (const float*)d_in[4];
    const float* Wp  = (const float*)d_in[5];
    const float* bp  = (const float*)d_in[6];
    const float* W1  = (const float*)d_in[7];
    const float* b1  = (const float*)d_in[8];
    const float* W2  = (const float*)d_in[9];
    const float* b2  = (const float*)d_in[10];
    float* out = (float*)d_out;

    cudaFuncSetAttribute(gru_kernel, cudaFuncAttributeMaxDynamicSharedMemorySize, SMEM_TOT);
    gru_kernel<<<VV * (BB / NB), NTHR, SMEM_TOT>>>(x, Wih, Whh, bih, bhh, Wp, bp);
    fc_kernel<<<BB, 256>>>(W1, b1, W2, b2, out);
}

// round 6
// speedup vs baseline: 2.9043x; 1.5491x over previous
#include <cuda_runtime.h>
#include <cuda_bf16.h>
#include <math.h>

#define VV 16
#define BB 64
#define TT 256
#define HH 128
#define GG 384
#define FCN 256
#define CC 10
#define NB 8            // batch rows per CTA = MMA N
#define NTHR 384        // 12 warps

// ---- smem byte offsets ----
#define OFF_WHI 0                        // W_hi bf16 [384][128] swizzled (reused as const table)
#define OFF_WLO (OFF_WHI + GG*256)       // 98304
#define OFF_HHI (OFF_WLO + GG*256)       // 196608: h_hi bf16 [8][128]
#define OFF_HLO (OFF_HHI + NB*256)       // 198656: h_lo
#define OFF_GH  (OFF_HLO + NB*256)       // 200704: gh f32 [384][8]
#define OFF_X   (OFF_GH + GG*NB*4)       // 212992: x f32 [8][256] (reused as hfin)
#define SMEM_TOT (OFF_X + NB*TT*4)       // 221184

typedef unsigned int u32;

__device__ float g_concat[BB * VV];

// XOR-swizzled byte offset within a [rows][128] bf16 tile (256B rows, 16B chunks)
__device__ __forceinline__ int swz(int r, int k) {
    return r * 256 + ((((k >> 3) ^ (r & 7)) & 15) << 4) + ((k & 7) << 1);
}

__device__ __forceinline__ u32 smem_u32(const void* p) {
    u32 a;
    asm("{ .reg .u64 t; cvta.to.shared.u64 t, %1; cvt.u32.u64 %0, t; }" : "=r"(a) : "l"(p));
    return a;
}

__device__ __forceinline__ void ldsm4(u32& a0, u32& a1, u32& a2, u32& a3, u32 addr) {
    asm volatile("ldmatrix.sync.aligned.m8n8.x4.shared.b16 {%0,%1,%2,%3}, [%4];"
                 : "=r"(a0), "=r"(a1), "=r"(a2), "=r"(a3) : "r"(addr));
}
__device__ __forceinline__ void ldsm2(u32& b0, u32& b1, u32 addr) {
    asm volatile("ldmatrix.sync.aligned.m8n8.x2.shared.b16 {%0,%1}, [%2];"
                 : "=r"(b0), "=r"(b1) : "r"(addr));
}
__device__ __forceinline__ void mma16816(float* d, u32 a0, u32 a1, u32 a2, u32 a3,
                                         u32 b0, u32 b1) {
    asm volatile("mma.sync.aligned.m16n8k16.row.col.f32.bf16.bf16.f32 "
                 "{%0,%1,%2,%3}, {%4,%5,%6,%7}, {%8,%9}, {%0,%1,%2,%3};"
                 : "+f"(d[0]), "+f"(d[1]), "+f"(d[2]), "+f"(d[3])
                 : "r"(a0), "r"(a1), "r"(a2), "r"(a3), "r"(b0), "r"(b1));
}

__device__ __forceinline__ float sigm_(float x) {
    return __fdividef(1.0f, 1.0f + __expf(-x));
}
__device__ __forceinline__ float tanh_(float x) {
    return fmaf(-2.0f, __fdividef(1.0f, __expf(2.0f * x) + 1.0f), 1.0f);
}

__global__ __launch_bounds__(NTHR, 1)
void gru_kernel(const float* __restrict__ x,   const float* __restrict__ Wih,
                const float* __restrict__ Whh, const float* __restrict__ bih,
                const float* __restrict__ bhh, const float* __restrict__ Wp,
                const float* __restrict__ bp)
{
    extern __shared__ char sm[];
    const u32 smb = smem_u32(sm);
    const int tid = threadIdx.x;
    const int v  = blockIdx.x >> 3;          // 16 variables
    const int b0 = (blockIdx.x & 7) * NB;    // 8 batch-groups of 8

    // ---- stage Whh[v] as bf16 hi/lo into swizzled tiles ----
    const float* Whh_v = Whh + (size_t)v * GG * HH;
    for (int idx = tid; idx < GG * HH; idx += NTHR) {
        int g = idx >> 7, k = idx & 127;
        float wv = Whh_v[idx];
        __nv_bfloat16 hi = __float2bfloat16(wv);
        __nv_bfloat16 lo = __float2bfloat16(wv - __bfloat162float(hi));
        int o = swz(g, k);
        *(__nv_bfloat16*)(sm + OFF_WHI + o) = hi;
        *(__nv_bfloat16*)(sm + OFF_WLO + o) = lo;
    }
    // ---- zero h tiles (h0 = 0) ----
    for (int idx = tid; idx < (2 * NB * 256) / 4; idx += NTHR)
        ((u32*)(sm + OFF_HHI))[idx] = 0u;
    // ---- stage x slice ----
    float* sXf = (float*)(sm + OFF_X);
    const float* x_v = x + (size_t)(v * BB + b0) * TT;
    for (int idx = tid; idx < NB * TT; idx += NTHR) sXf[idx] = x_v[idx];

    // ---- phase-1 lane geometry ----
    const int w = tid >> 5, L = tid & 31;
    const int rowl  = ((L >> 3) & 1) * 8 + (L & 7);
    const int khalf = (L >> 4) & 1;
    const int xr    = L & 7;
    const int nrow  = L & 7;
    const int csel  = (L >> 3) & 1;
    const u32 aHi0 = smb + OFF_WHI + (u32)(32 * w + rowl) * 256;
    const u32 aHi1 = aHi0 + 16 * 256;
    const u32 aLo0 = aHi0 + (OFF_WLO - OFF_WHI);
    const u32 aLo1 = aHi1 + (OFF_WLO - OFF_WHI);
    const u32 bHiB = smb + OFF_HHI + (u32)nrow * 256;
    const u32 bLoB = bHiB + NB * 256;
    const int quad = L >> 2, qc = L & 3;

    const int j   = tid & 127;
    const int sub = tid >> 7;      // 0..2; phase-2 active iff tid<256

    __syncthreads();

    // ---- preload ALL A fragments into registers (weights constant over t) ----
    u32 ah0[8][4], ah1[8][4], al0[8][4], al1[8][4];
    #pragma unroll
    for (int s = 0; s < 8; s++) {
        const u32 ca = (u32)((((2 * s + khalf) ^ xr) & 15) << 4);
        ldsm4(ah0[s][0], ah0[s][1], ah0[s][2], ah0[s][3], aHi0 + ca);
        ldsm4(ah1[s][0], ah1[s][1], ah1[s][2], ah1[s][3], aHi1 + ca);
        ldsm4(al0[s][0], al0[s][1], al0[s][2], al0[s][3], aLo0 + ca);
        ldsm4(al1[s][0], al1[s][1], al1[s][2], al1[s][3], aLo1 + ca);
    }
    __syncthreads();

    // ---- phase-2 constants -> smem table (reuse the now-dead W_hi region) ----
    float* sPC = (float*)(sm + OFF_WHI);   // 7 arrays of 128 floats
    if (tid < 128) {
        sPC[tid]       = Wih[v * GG + tid];
        sPC[128 + tid] = Wih[v * GG + 128 + tid];
        sPC[256 + tid] = Wih[v * GG + 256 + tid];
        sPC[384 + tid] = bih[v * GG + tid]       + bhh[v * GG + tid];
        sPC[512 + tid] = bih[v * GG + 128 + tid] + bhh[v * GG + 128 + tid];
        sPC[640 + tid] = bih[v * GG + 256 + tid];
        sPC[768 + tid] = bhh[v * GG + 256 + tid];
    }
    float hreg[4] = {0.f, 0.f, 0.f, 0.f};
    __syncthreads();

    for (int t = 0; t < TT; t++) {
        // ============ phase 1: gh = Whi*hhi + Whi*hlo + Wlo*hhi (HMMA) ============
        float acc0[4] = {0.f, 0.f, 0.f, 0.f};
        float acc1[4] = {0.f, 0.f, 0.f, 0.f};
        #pragma unroll
        for (int s = 0; s < 8; s++) {
            const u32 cb = (u32)((((2 * s + csel) ^ nrow) & 15) << 4);
            u32 bh0, bh1, bl0, bl1;
            ldsm2(bh0, bh1, bHiB + cb);
            ldsm2(bl0, bl1, bLoB + cb);
            mma16816(acc0, ah0[s][0], ah0[s][1], ah0[s][2], ah0[s][3], bh0, bh1);
            mma16816(acc1, ah1[s][0], ah1[s][1], ah1[s][2], ah1[s][3], bh0, bh1);
            mma16816(acc0, ah0[s][0], ah0[s][1], ah0[s][2], ah0[s][3], bl0, bl1);
            mma16816(acc1, ah1[s][0], ah1[s][1], ah1[s][2], ah1[s][3], bl0, bl1);
            mma16816(acc0, al0[s][0], al0[s][1], al0[s][2], al0[s][3], bh0, bh1);
            mma16816(acc1, al1[s][0], al1[s][1], al1[s][2], al1[s][3], bh0, bh1);
        }
        // store gh tiles: D[row][col] -> sGH[g][b]
        {
            char* gh = sm + OFF_GH;
            int g00 = 32 * w + quad;
            *(float2*)(gh + (g00)      * 32 + qc * 8) = make_float2(acc0[0], acc0[1]);
            *(float2*)(gh + (g00 + 8)  * 32 + qc * 8) = make_float2(acc0[2], acc0[3]);
            *(float2*)(gh + (g00 + 16) * 32 + qc * 8) = make_float2(acc1[0], acc1[1]);
            *(float2*)(gh + (g00 + 24) * 32 + qc * 8) = make_float2(acc1[2], acc1[3]);
        }
        __syncthreads();

        // ============ phase 2: gates + state update (256 threads) ============
        if (tid < 256) {
            const char* gh = sm + OFF_GH;
            float4 g_r = *(const float4*)(gh + (size_t)j * 32 + sub * 16);
            float4 g_z = *(const float4*)(gh + (size_t)(128 + j) * 32 + sub * 16);
            float4 g_n = *(const float4*)(gh + (size_t)(256 + j) * 32 + sub * 16);
            float ghr[4] = {g_r.x, g_r.y, g_r.z, g_r.w};
            float ghz[4] = {g_z.x, g_z.y, g_z.z, g_z.w};
            float ghn[4] = {g_n.x, g_n.y, g_n.z, g_n.w};
            const float wr = sPC[j],       wz = sPC[128 + j], wn = sPC[256 + j];
            const float br = sPC[384 + j], bz = sPC[512 + j];
            const float bi_n = sPC[640 + j], bh_n = sPC[768 + j];
            #pragma unroll
            for (int i = 0; i < 4; i++) {
                int b = 4 * sub + i;
                float xv = sXf[b * TT + t];
                float rg = sigm_(fmaf(xv, wr, br) + ghr[i]);
                float zg = sigm_(fmaf(xv, wz, bz) + ghz[i]);
                float ng = tanh_(fmaf(xv, wn, bi_n) + rg * (ghn[i] + bh_n));
                float hn = fmaf(zg, hreg[i] - ng, ng);     // (1-z)*n + z*h
                hreg[i] = hn;
                __nv_bfloat16 hi16 = __float2bfloat16(hn);
                __nv_bfloat16 lo16 = __float2bfloat16(hn - __bfloat162float(hi16));
                int o = swz(b, j);
                *(__nv_bfloat16*)(sm + OFF_HHI + o) = hi16;
                *(__nv_bfloat16*)(sm + OFF_HLO + o) = lo16;
            }
        }
        __syncthreads();
    }

    // ============ epilogue: concat[b][v] ============
    float* hfin = (float*)(sm + OFF_X);   // reuse x region: [8][128] f32
    if (tid < 256) {
        #pragma unroll
        for (int i = 0; i < 4; i++) hfin[(4 * sub + i) * HH + j] = hreg[i];
    }
    __syncthreads();

    if (w < NB) {
        const float* Wp_v = Wp + v * HH;
        float s = 0.0f;
        #pragma unroll
        for (int q = 0; q < 4; q++) {
            int jj = L + 32 * q;
            s = fmaf(hfin[w * HH + jj], Wp_v[jj], s);
        }
        #pragma unroll
        for (int off = 16; off; off >>= 1) s += __shfl_xor_sync(0xffffffffu, s, off);
        if (L == 0) g_concat[(b0 + w) * VV + v] = s + bp[v];
    }
}

// one CTA per batch row; warp-per-class output reduction
__global__ __launch_bounds__(256, 1)
void fc_kernel(const float* __restrict__ W1, const float* __restrict__ b1,
               const float* __restrict__ W2, const float* __restrict__ b2,
               float* __restrict__ out)
{
    __shared__ float sC[VV];
    __shared__ float sF[FCN];

    const int b = blockIdx.x;
    const int tid = threadIdx.x;

    if (tid < VV) sC[tid] = g_concat[b * VV + tid];
    __syncthreads();

    {
        float a = b1[tid];
        const float* w1 = W1 + tid * VV;
        #pragma unroll
        for (int vv = 0; vv < VV; vv++) a = fmaf(sC[vv], w1[vv], a);
        sF[tid] = fmaxf(a, 0.0f);
    }
    __syncthreads();

    const int wid = tid >> 5, lane = tid & 31;
    for (int c = wid; c < CC; c += 8) {
        const float* w2 = W2 + c * FCN;
        float a = 0.0f;
        #pragma unroll
        for (int q = 0; q < FCN / 32; q++) {
            int f = lane + 32 * q;
            a = fmaf(sF[f], w2[f], a);
        }
        #pragma unroll
        for (int off = 16; off; off >>= 1) a += __shfl_xor_sync(0xffffffffu, a, off);
        if (lane == 0) out[b * CC + c] = a + b2[c];
    }
}

extern "C" void kernel_launch(void* const* d_in, const int* in_sizes, int n_in,
                              void* d_out, int out_size)
{
    const float* x   = (const float*)d_in[0];
    const float* Wih = (const float*)d_in[1];
    const float* Whh = (const float*)d_in[2];
    const float* bih = (const float*)d_in[3];
    const float* bhh = (const float*)d_in[4];
    const float* Wp  = (const float*)d_in[5];
    const float* bp  = (const float*)d_in[6];
    const float* W1  = (const float*)d_in[7];
    const float* b1  = (const float*)d_in[8];
    const float* W2  = (const float*)d_in[9];
    const float* b2  = (const float*)d_in[10];
    float* out = (float*)d_out;

    cudaFuncSetAttribute(gru_kernel, cudaFuncAttributeMaxDynamicSharedMemorySize, SMEM_TOT);
    gru_kernel<<<VV * (BB / NB), NTHR, SMEM_TOT>>>(x, Wih, Whh, bih, bhh, Wp, bp);
    fc_kernel<<<BB, 256>>>(W1, b1, W2, b2, out);
}

// round 7
// speedup vs baseline: 3.3211x; 1.1435x over previous
#include <cuda_runtime.h>
#include <cuda_bf16.h>
#include <math.h>

#define VV 16
#define BB 64
#define TT 256
#define HH 128
#define GG 384
#define FCN 256
#define CC 10
#define NB 8            // batch rows per CTA = MMA N
#define NTHR 384        // 12 warps

// ---- smem byte offsets ----
#define OFF_WHI 0                        // W_hi bf16 [384][128] swizzled (reused as const table)
#define OFF_WLO (OFF_WHI + GG*256)       // 98304
#define OFF_HHI (OFF_WLO + GG*256)       // 196608: h_hi bf16 [8][128]
#define OFF_HLO (OFF_HHI + NB*256)       // 198656: h_lo
#define OFF_GH  (OFF_HLO + NB*256)       // 200704: gh f32 [384][8]
#define OFF_X   (OFF_GH + GG*NB*4)       // 212992: x f32 [8][256] (reused as hfin)
#define SMEM_TOT (OFF_X + NB*TT*4)       // 221184

typedef unsigned int u32;

__device__ float g_concat[BB * VV];

// XOR-swizzled byte offset within a [rows][128] bf16 tile (256B rows, 16B chunks)
__device__ __forceinline__ int swz(int r, int k) {
    return r * 256 + ((((k >> 3) ^ (r & 7)) & 15) << 4) + ((k & 7) << 1);
}

__device__ __forceinline__ u32 smem_u32(const void* p) {
    u32 a;
    asm("{ .reg .u64 t; cvta.to.shared.u64 t, %1; cvt.u32.u64 %0, t; }" : "=r"(a) : "l"(p));
    return a;
}

__device__ __forceinline__ void ldsm4(u32& a0, u32& a1, u32& a2, u32& a3, u32 addr) {
    asm volatile("ldmatrix.sync.aligned.m8n8.x4.shared.b16 {%0,%1,%2,%3}, [%4];"
                 : "=r"(a0), "=r"(a1), "=r"(a2), "=r"(a3) : "r"(addr));
}
__device__ __forceinline__ void ldsm2(u32& b0, u32& b1, u32 addr) {
    asm volatile("ldmatrix.sync.aligned.m8n8.x2.shared.b16 {%0,%1}, [%2];"
                 : "=r"(b0), "=r"(b1) : "r"(addr));
}
__device__ __forceinline__ void mma16816(float* d, u32 a0, u32 a1, u32 a2, u32 a3,
                                         u32 b0, u32 b1) {
    asm volatile("mma.sync.aligned.m16n8k16.row.col.f32.bf16.bf16.f32 "
                 "{%0,%1,%2,%3}, {%4,%5,%6,%7}, {%8,%9}, {%0,%1,%2,%3};"
                 : "+f"(d[0]), "+f"(d[1]), "+f"(d[2]), "+f"(d[3])
                 : "r"(a0), "r"(a1), "r"(a2), "r"(a3), "r"(b0), "r"(b1));
}

__device__ __forceinline__ float tanha_(float x) {
    float y;
    asm("tanh.approx.f32 %0, %1;" : "=f"(y) : "f"(x));
    return y;
}
__device__ __forceinline__ float sigm_(float x) {
    return fmaf(0.5f, tanha_(0.5f * x), 0.5f);
}

__global__ __launch_bounds__(NTHR, 1)
void gru_kernel(const float* __restrict__ x,   const float* __restrict__ Wih,
                const float* __restrict__ Whh, const float* __restrict__ bih,
                const float* __restrict__ bhh, const float* __restrict__ Wp,
                const float* __restrict__ bp)
{
    extern __shared__ char sm[];
    const u32 smb = smem_u32(sm);
    const int tid = threadIdx.x;
    const int v  = blockIdx.x >> 3;          // 16 variables
    const int b0 = (blockIdx.x & 7) * NB;    // 8 batch-groups of 8

    // ---- stage Whh[v] as bf16 hi/lo into swizzled tiles ----
    const float* Whh_v = Whh + (size_t)v * GG * HH;
    for (int idx = tid; idx < GG * HH; idx += NTHR) {
        int g = idx >> 7, k = idx & 127;
        float wv = Whh_v[idx];
        __nv_bfloat16 hi = __float2bfloat16(wv);
        __nv_bfloat16 lo = __float2bfloat16(wv - __bfloat162float(hi));
        int o = swz(g, k);
        *(__nv_bfloat16*)(sm + OFF_WHI + o) = hi;
        *(__nv_bfloat16*)(sm + OFF_WLO + o) = lo;
    }
    // ---- zero h tiles (h0 = 0) ----
    for (int idx = tid; idx < (2 * NB * 256) / 4; idx += NTHR)
        ((u32*)(sm + OFF_HHI))[idx] = 0u;
    // ---- stage x slice ----
    float* sXf = (float*)(sm + OFF_X);
    const float* x_v = x + (size_t)(v * BB + b0) * TT;
    for (int idx = tid; idx < NB * TT; idx += NTHR) sXf[idx] = x_v[idx];

    // ---- phase-1 lane geometry ----
    const int w = tid >> 5, L = tid & 31;
    const int rowl  = ((L >> 3) & 1) * 8 + (L & 7);
    const int khalf = (L >> 4) & 1;
    const int xr    = L & 7;
    const int nrow  = L & 7;
    const int csel  = (L >> 3) & 1;
    const u32 aHi0 = smb + OFF_WHI + (u32)(32 * w + rowl) * 256;
    const u32 aHi1 = aHi0 + 16 * 256;
    const u32 aLo0 = aHi0 + (OFF_WLO - OFF_WHI);
    const u32 aLo1 = aHi1 + (OFF_WLO - OFF_WHI);
    const u32 bHiB = smb + OFF_HHI + (u32)nrow * 256;
    const u32 bLoB = bHiB + NB * 256;
    const int quad = L >> 2, qc = L & 3;

    const int j   = tid & 127;
    const int sub = tid >> 7;      // 0..2; phase-2 active iff tid<256

    __syncthreads();

    // ---- preload ALL A fragments into registers (weights constant over t) ----
    u32 ah0[8][4], ah1[8][4], al0[8][4], al1[8][4];
    #pragma unroll
    for (int s = 0; s < 8; s++) {
        const u32 ca = (u32)((((2 * s + khalf) ^ xr) & 15) << 4);
        ldsm4(ah0[s][0], ah0[s][1], ah0[s][2], ah0[s][3], aHi0 + ca);
        ldsm4(ah1[s][0], ah1[s][1], ah1[s][2], ah1[s][3], aHi1 + ca);
        ldsm4(al0[s][0], al0[s][1], al0[s][2], al0[s][3], aLo0 + ca);
        ldsm4(al1[s][0], al1[s][1], al1[s][2], al1[s][3], aLo1 + ca);
    }
    __syncthreads();

    // ---- phase-2 constants -> smem table (reuse the now-dead W_hi region) ----
    float* sPC = (float*)(sm + OFF_WHI);   // 7 arrays of 128 floats
    if (tid < 128) {
        sPC[tid]       = Wih[v * GG + tid];
        sPC[128 + tid] = Wih[v * GG + 128 + tid];
        sPC[256 + tid] = Wih[v * GG + 256 + tid];
        sPC[384 + tid] = bih[v * GG + tid]       + bhh[v * GG + tid];
        sPC[512 + tid] = bih[v * GG + 128 + tid] + bhh[v * GG + 128 + tid];
        sPC[640 + tid] = bih[v * GG + 256 + tid];
        sPC[768 + tid] = bhh[v * GG + 256 + tid];
    }
    float hreg[4] = {0.f, 0.f, 0.f, 0.f};
    __syncthreads();

    // B chunk-select offsets (precomputed per s)
    u32 cbo[8];
    #pragma unroll
    for (int s = 0; s < 8; s++)
        cbo[s] = (u32)((((2 * s + csel) ^ nrow) & 15) << 4);

    for (int t = 0; t < TT; t++) {
        // ============ phase 1: gh = Whi*hhi + Whi*hlo + Wlo*hhi (HMMA) ============
        float acc0[4] = {0.f, 0.f, 0.f, 0.f};
        float acc1[4] = {0.f, 0.f, 0.f, 0.f};
        // software-pipelined B fragments (double-buffered)
        u32 bh0[2], bh1[2], bl0[2], bl1[2];
        ldsm2(bh0[0], bh1[0], bHiB + cbo[0]);
        ldsm2(bl0[0], bl1[0], bLoB + cbo[0]);
        #pragma unroll
        for (int s = 0; s < 8; s++) {
            const int cu = s & 1, nx = cu ^ 1;
            if (s < 7) {
                ldsm2(bh0[nx], bh1[nx], bHiB + cbo[s + 1]);
                ldsm2(bl0[nx], bl1[nx], bLoB + cbo[s + 1]);
            }
            mma16816(acc0, ah0[s][0], ah0[s][1], ah0[s][2], ah0[s][3], bh0[cu], bh1[cu]);
            mma16816(acc1, ah1[s][0], ah1[s][1], ah1[s][2], ah1[s][3], bh0[cu], bh1[cu]);
            mma16816(acc0, ah0[s][0], ah0[s][1], ah0[s][2], ah0[s][3], bl0[cu], bl1[cu]);
            mma16816(acc1, ah1[s][0], ah1[s][1], ah1[s][2], ah1[s][3], bl0[cu], bl1[cu]);
            mma16816(acc0, al0[s][0], al0[s][1], al0[s][2], al0[s][3], bh0[cu], bh1[cu]);
            mma16816(acc1, al1[s][0], al1[s][1], al1[s][2], al1[s][3], bh0[cu], bh1[cu]);
        }
        // store gh tiles: D[row][col] -> sGH[g][b]
        {
            char* gh = sm + OFF_GH;
            int g00 = 32 * w + quad;
            *(float2*)(gh + (g00)      * 32 + qc * 8) = make_float2(acc0[0], acc0[1]);
            *(float2*)(gh + (g00 + 8)  * 32 + qc * 8) = make_float2(acc0[2], acc0[3]);
            *(float2*)(gh + (g00 + 16) * 32 + qc * 8) = make_float2(acc1[0], acc1[1]);
            *(float2*)(gh + (g00 + 24) * 32 + qc * 8) = make_float2(acc1[2], acc1[3]);
        }
        __syncthreads();

        // ============ phase 2: gates + state update (256 threads) ============
        if (tid < 256) {
            const char* gh = sm + OFF_GH;
            float4 g_r = *(const float4*)(gh + (size_t)j * 32 + sub * 16);
            float4 g_z = *(const float4*)(gh + (size_t)(128 + j) * 32 + sub * 16);
            float4 g_n = *(const float4*)(gh + (size_t)(256 + j) * 32 + sub * 16);
            float ghr[4] = {g_r.x, g_r.y, g_r.z, g_r.w};
            float ghz[4] = {g_z.x, g_z.y, g_z.z, g_z.w};
            float ghn[4] = {g_n.x, g_n.y, g_n.z, g_n.w};
            const float wr = sPC[j],       wz = sPC[128 + j], wn = sPC[256 + j];
            const float br = sPC[384 + j], bz = sPC[512 + j];
            const float bi_n = sPC[640 + j], bh_n = sPC[768 + j];
            #pragma unroll
            for (int i = 0; i < 4; i++) {
                int b = 4 * sub + i;
                float xv = sXf[b * TT + t];
                float rg = sigm_(fmaf(xv, wr, br) + ghr[i]);
                float zg = sigm_(fmaf(xv, wz, bz) + ghz[i]);
                float ng = tanha_(fmaf(xv, wn, bi_n) + rg * (ghn[i] + bh_n));
                float hn = fmaf(zg, hreg[i] - ng, ng);     // (1-z)*n + z*h
                hreg[i] = hn;
                __nv_bfloat16 hi16 = __float2bfloat16(hn);
                __nv_bfloat16 lo16 = __float2bfloat16(hn - __bfloat162float(hi16));
                int o = swz(b, j);
                *(__nv_bfloat16*)(sm + OFF_HHI + o) = hi16;
                *(__nv_bfloat16*)(sm + OFF_HLO + o) = lo16;
            }
        }
        __syncthreads();
    }

    // ============ epilogue: concat[b][v] ============
    float* hfin = (float*)(sm + OFF_X);   // reuse x region: [8][128] f32
    if (tid < 256) {
        #pragma unroll
        for (int i = 0; i < 4; i++) hfin[(4 * sub + i) * HH + j] = hreg[i];
    }
    __syncthreads();

    if (w < NB) {
        const float* Wp_v = Wp + v * HH;
        float s = 0.0f;
        #pragma unroll
        for (int q = 0; q < 4; q++) {
            int jj = L + 32 * q;
            s = fmaf(hfin[w * HH + jj], Wp_v[jj], s);
        }
        #pragma unroll
        for (int off = 16; off; off >>= 1) s += __shfl_xor_sync(0xffffffffu, s, off);
        if (L == 0) g_concat[(b0 + w) * VV + v] = s + bp[v];
    }
}

// one CTA per batch row; warp-per-class output reduction
__global__ __launch_bounds__(256, 1)
void fc_kernel(const float* __restrict__ W1, const float* __restrict__ b1,
               const float* __restrict__ W2, const float* __restrict__ b2,
               float* __restrict__ out)
{
    __shared__ float sC[VV];
    __shared__ float sF[FCN];

    const int b = blockIdx.x;
    const int tid = threadIdx.x;

    if (tid < VV) sC[tid] = g_concat[b * VV + tid];
    __syncthreads();

    {
        float a = b1[tid];
        const float* w1 = W1 + tid * VV;
        #pragma unroll
        for (int vv = 0; vv < VV; vv++) a = fmaf(sC[vv], w1[vv], a);
        sF[tid] = fmaxf(a, 0.0f);
    }
    __syncthreads();

    const int wid = tid >> 5, lane = tid & 31;
    for (int c = wid; c < CC; c += 8) {
        const float* w2 = W2 + c * FCN;
        float a = 0.0f;
        #pragma unroll
        for (int q = 0; q < FCN / 32; q++) {
            int f = lane + 32 * q;
            a = fmaf(sF[f], w2[f], a);
        }
        #pragma unroll
        for (int off = 16; off; off >>= 1) a += __shfl_xor_sync(0xffffffffu, a, off);
        if (lane == 0) out[b * CC + c] = a + b2[c];
    }
}

// diagnostic no-op launches: pad to 5 launches/call so ncu (-s 5 -c 1) lands on gru_kernel
__global__ void nop_kernel() {}

extern "C" void kernel_launch(void* const* d_in, const int* in_sizes, int n_in,
                              void* d_out, int out_size)
{
    const float* x   = (const float*)d_in[0];
    const float* Wih = (const float*)d_in[1];
    const float* Whh = (const float*)d_in[2];
    const float* bih = (const float*)d_in[3];
    const float* bhh = (const float*)d_in[4];
    const float* Wp  = (const float*)d_in[5];
    const float* bp  = (const float*)d_in[6];
    const float* W1  = (const float*)d_in[7];
    const float* b1  = (const float*)d_in[8];
    const float* W2  = (const float*)d_in[9];
    const float* b2  = (const float*)d_in[10];
    float* out = (float*)d_out;

    cudaFuncSetAttribute(gru_kernel, cudaFuncAttributeMaxDynamicSharedMemorySize, SMEM_TOT);
    gru_kernel<<<VV * (BB / NB), NTHR, SMEM_TOT>>>(x, Wih, Whh, bih, bhh, Wp, bp);
    fc_kernel<<<BB, 256>>>(W1, b1, W2, b2, out);
    nop_kernel<<<1, 32>>>();
    nop_kernel<<<1, 32>>>();
    nop_kernel<<<1, 32>>>();
}

// round 8
// speedup vs baseline: 3.7255x; 1.1218x over previous
#include <cuda_runtime.h>
#include <cuda_bf16.h>
#include <math.h>

#define VV 16
#define BB 64
#define TT 256
#define HH 128
#define GG 384
#define FCN 256
#define CC 10
#define NB 8            // batch rows per CTA = MMA N
#define NTHR 384        // 12 warps

// ---- smem byte offsets ----
#define OFF_WHI 0                        // W_hi bf16 [384][128] swizzled (reused as const table)
#define OFF_WLO (OFF_WHI + GG*256)       // 98304
#define OFF_HHI (OFF_WLO + GG*256)       // 196608: h_hi bf16 [8][128]
#define OFF_HLO (OFF_HHI + NB*256)       // 198656: h_lo
#define OFF_GH  (OFF_HLO + NB*256)       // 200704: gh f32 [3][8][132] padded
#define GH_SZ   (3*NB*132*4)             // 12672
#define OFF_X   (OFF_GH + GH_SZ)         // x f32 [8][256] (reused as hfin)
#define SMEM_TOT (OFF_X + NB*TT*4)       // 221568

typedef unsigned int u32;

__device__ float g_concat[BB * VV];

// XOR-swizzled byte offset within a [rows][128] bf16 tile (256B rows, 16B chunks)
__device__ __forceinline__ int swz(int r, int k) {
    return r * 256 + ((((k >> 3) ^ (r & 7)) & 15) << 4) + ((k & 7) << 1);
}

__device__ __forceinline__ u32 smem_u32(const void* p) {
    u32 a;
    asm("{ .reg .u64 t; cvta.to.shared.u64 t, %1; cvt.u32.u64 %0, t; }" : "=r"(a) : "l"(p));
    return a;
}

__device__ __forceinline__ void ldsm4(u32& a0, u32& a1, u32& a2, u32& a3, u32 addr) {
    asm volatile("ldmatrix.sync.aligned.m8n8.x4.shared.b16 {%0,%1,%2,%3}, [%4];"
                 : "=r"(a0), "=r"(a1), "=r"(a2), "=r"(a3) : "r"(addr));
}
__device__ __forceinline__ void mma16816(float* d, const u32* a, u32 b0, u32 b1) {
    asm volatile("mma.sync.aligned.m16n8k16.row.col.f32.bf16.bf16.f32 "
                 "{%0,%1,%2,%3}, {%4,%5,%6,%7}, {%8,%9}, {%0,%1,%2,%3};"
                 : "+f"(d[0]), "+f"(d[1]), "+f"(d[2]), "+f"(d[3])
                 : "r"(a[0]), "r"(a[1]), "r"(a[2]), "r"(a[3]), "r"(b0), "r"(b1));
}

__device__ __forceinline__ float tanha_(float x) {
    float y;
    asm("tanh.approx.f32 %0, %1;" : "=f"(y) : "f"(x));
    return y;
}
__device__ __forceinline__ float sigm_(float x) {
    return fmaf(0.5f, tanha_(0.5f * x), 0.5f);
}

__global__ __launch_bounds__(NTHR, 1)
void gru_kernel(const float* __restrict__ x,   const float* __restrict__ Wih,
                const float* __restrict__ Whh, const float* __restrict__ bih,
                const float* __restrict__ bhh, const float* __restrict__ Wp,
                const float* __restrict__ bp)
{
    extern __shared__ char sm[];
    const u32 smb = smem_u32(sm);
    const int tid = threadIdx.x;
    const int v  = blockIdx.x >> 3;          // 16 variables
    const int b0 = (blockIdx.x & 7) * NB;    // 8 batch-groups of 8

    // ---- stage Whh[v] as bf16 hi/lo into swizzled tiles ----
    const float* Whh_v = Whh + (size_t)v * GG * HH;
    for (int idx = tid; idx < GG * HH; idx += NTHR) {
        int g = idx >> 7, k = idx & 127;
        float wv = Whh_v[idx];
        __nv_bfloat16 hi = __float2bfloat16(wv);
        __nv_bfloat16 lo = __float2bfloat16(wv - __bfloat162float(hi));
        int o = swz(g, k);
        *(__nv_bfloat16*)(sm + OFF_WHI + o) = hi;
        *(__nv_bfloat16*)(sm + OFF_WLO + o) = lo;
    }
    // ---- zero h tiles (h0 = 0) ----
    for (int idx = tid; idx < (2 * NB * 256) / 4; idx += NTHR)
        ((u32*)(sm + OFF_HHI))[idx] = 0u;
    // ---- stage x slice ----
    float* sXf = (float*)(sm + OFF_X);
    const float* x_v = x + (size_t)(v * BB + b0) * TT;
    for (int idx = tid; idx < NB * TT; idx += NTHR) sXf[idx] = x_v[idx];

    // ---- phase-1 lane geometry ----
    const int w = tid >> 5, L = tid & 31;
    const int rowl  = ((L >> 3) & 1) * 8 + (L & 7);
    const int khalf = (L >> 4) & 1;
    const int xr    = L & 7;
    const u32 aHi0 = smb + OFF_WHI + (u32)(32 * w + rowl) * 256;
    const u32 aHi1 = aHi0 + 16 * 256;
    const u32 aLo0 = aHi0 + (OFF_WLO - OFF_WHI);
    const u32 aLo1 = aHi1 + (OFF_WLO - OFF_WHI);
    // fused B ldsm4 addressing: lanes 0-15 -> h_hi (k-chunks), lanes 16-31 -> h_lo
    const int nrow = L & 7;
    const int half = (L >> 3) & 1;
    const int losel = (L >> 4) & 1;
    const u32 bBase = smb + (losel ? OFF_HLO : OFF_HHI) + (u32)nrow * 256;
    const int quad = L >> 2, qc = L & 3;

    __syncthreads();

    // ---- preload ALL A fragments into registers (weights constant over t) ----
    u32 ah0[8][4], ah1[8][4], al0[8][4], al1[8][4];
    #pragma unroll
    for (int s = 0; s < 8; s++) {
        const u32 ca = (u32)((((2 * s + khalf) ^ xr) & 15) << 4);
        ldsm4(ah0[s][0], ah0[s][1], ah0[s][2], ah0[s][3], aHi0 + ca);
        ldsm4(ah1[s][0], ah1[s][1], ah1[s][2], ah1[s][3], aHi1 + ca);
        ldsm4(al0[s][0], al0[s][1], al0[s][2], al0[s][3], aLo0 + ca);
        ldsm4(al1[s][0], al1[s][1], al1[s][2], al1[s][3], aLo1 + ca);
    }
    __syncthreads();

    // ---- phase-2 constants -> smem table (reuse the now-dead W_hi region) ----
    float* sPC = (float*)(sm + OFF_WHI);   // 7 arrays of 128 floats
    if (tid < 128) {
        sPC[tid]       = Wih[v * GG + tid];
        sPC[128 + tid] = Wih[v * GG + 128 + tid];
        sPC[256 + tid] = Wih[v * GG + 256 + tid];
        sPC[384 + tid] = bih[v * GG + tid]       + bhh[v * GG + tid];
        sPC[512 + tid] = bih[v * GG + 128 + tid] + bhh[v * GG + 128 + tid];
        sPC[640 + tid] = bih[v * GG + 256 + tid];
        sPC[768 + tid] = bhh[v * GG + 256 + tid];
    }

    // ---- phase-2 mapping: fixed j per thread, b strided by 3 ----
    const int j  = tid & 127;
    const int bA = tid >> 7;              // first b: 0,1,2
    const int nE = (bA < 2) ? 3 : 2;      // b set: {bA, bA+3, bA+6} clipped at 8
    float hreg[3] = {0.f, 0.f, 0.f};

    // phase-1 B chunk offsets per s (per-lane)
    u32 cbo[8];
    #pragma unroll
    for (int s = 0; s < 8; s++)
        cbo[s] = (u32)((((2 * s + half) ^ nrow) & 15) << 4);

    float* gh = (float*)(sm + OFF_GH);
    const int gate_w = w >> 2;                 // warp's gate 0..2
    const int j0 = (w & 3) * 32 + quad;        // warp-lane's gate-local j row
    float* ghW = gh + gate_w * (NB * 132) + j0;

    __syncthreads();

    for (int t = 0; t < TT; t++) {
        // ============ phase 1: gh = Whi*hhi + Whi*hlo + Wlo*hhi (HMMA) ============
        float acc0[4] = {0.f, 0.f, 0.f, 0.f};
        float acc1[4] = {0.f, 0.f, 0.f, 0.f};
        u32 bh0[2], bh1[2], bl0[2], bl1[2];
        ldsm4(bh0[0], bh1[0], bl0[0], bl1[0], bBase + cbo[0]);
        #pragma unroll
        for (int s = 0; s < 8; s++) {
            const int cu = s & 1, nx = cu ^ 1;
            if (s < 7) ldsm4(bh0[nx], bh1[nx], bl0[nx], bl1[nx], bBase + cbo[s + 1]);
            mma16816(acc0, ah0[s], bh0[cu], bh1[cu]);
            mma16816(acc1, ah1[s], bh0[cu], bh1[cu]);
            mma16816(acc0, ah0[s], bl0[cu], bl1[cu]);
            mma16816(acc1, ah1[s], bl0[cu], bl1[cu]);
            mma16816(acc0, al0[s], bh0[cu], bh1[cu]);
            mma16816(acc1, al1[s], bh0[cu], bh1[cu]);
        }
        // store gh -> [gate][b(stride132)][j]
        {
            const int c0 = 2 * qc, c1 = 2 * qc + 1;
            ghW[c0 * 132 + 0]  = acc0[0];  ghW[c1 * 132 + 0]  = acc0[1];
            ghW[c0 * 132 + 8]  = acc0[2];  ghW[c1 * 132 + 8]  = acc0[3];
            ghW[c0 * 132 + 16] = acc1[0];  ghW[c1 * 132 + 16] = acc1[1];
            ghW[c0 * 132 + 24] = acc1[2];  ghW[c1 * 132 + 24] = acc1[3];
        }
        __syncthreads();

        // ============ phase 2: gates + state update (ALL 384 threads) ============
        {
            const float wr = sPC[j],       wz = sPC[128 + j], wn = sPC[256 + j];
            const float br = sPC[384 + j], bz = sPC[512 + j];
            const float bi_n = sPC[640 + j], bh_n = sPC[768 + j];
            #pragma unroll
            for (int q = 0; q < 3; q++) {
                if (q < nE) {
                    const int b = bA + 3 * q;
                    float ghr = gh[b * 132 + j];
                    float ghz = gh[NB * 132 + b * 132 + j];
                    float ghn = gh[2 * NB * 132 + b * 132 + j];
                    float xv  = sXf[b * TT + t];
                    float rg = sigm_(fmaf(xv, wr, br) + ghr);
                    float zg = sigm_(fmaf(xv, wz, bz) + ghz);
                    float ng = tanha_(fmaf(xv, wn, bi_n) + rg * (ghn + bh_n));
                    float hn = fmaf(zg, hreg[q] - ng, ng);     // (1-z)*n + z*h
                    hreg[q] = hn;
                    __nv_bfloat16 hi16 = __float2bfloat16(hn);
                    __nv_bfloat16 lo16 = __float2bfloat16(hn - __bfloat162float(hi16));
                    int o = swz(b, j);
                    *(__nv_bfloat16*)(sm + OFF_HHI + o) = hi16;
                    *(__nv_bfloat16*)(sm + OFF_HLO + o) = lo16;
                }
            }
        }
        __syncthreads();
    }

    // ============ epilogue: concat[b][v] ============
    float* hfin = (float*)(sm + OFF_X);   // reuse x region: [8][128] f32
    #pragma unroll
    for (int q = 0; q < 3; q++)
        if (q < nE) hfin[(bA + 3 * q) * HH + j] = hreg[q];
    __syncthreads();

    if (w < NB) {
        const float* Wp_v = Wp + v * HH;
        float s = 0.0f;
        #pragma unroll
        for (int q = 0; q < 4; q++) {
            int jj = L + 32 * q;
            s = fmaf(hfin[w * HH + jj], Wp_v[jj], s);
        }
        #pragma unroll
        for (int off = 16; off; off >>= 1) s += __shfl_xor_sync(0xffffffffu, s, off);
        if (L == 0) g_concat[(b0 + w) * VV + v] = s + bp[v];
    }
}

// one CTA per batch row; warp-per-class output reduction
__global__ __launch_bounds__(256, 1)
void fc_kernel(const float* __restrict__ W1, const float* __restrict__ b1,
               const float* __restrict__ W2, const float* __restrict__ b2,
               float* __restrict__ out)
{
    __shared__ float sC[VV];
    __shared__ float sF[FCN];

    const int b = blockIdx.x;
    const int tid = threadIdx.x;

    if (tid < VV) sC[tid] = g_concat[b * VV + tid];
    __syncthreads();

    {
        float a = b1[tid];
        const float* w1 = W1 + tid * VV;
        #pragma unroll
        for (int vv = 0; vv < VV; vv++) a = fmaf(sC[vv], w1[vv], a);
        sF[tid] = fmaxf(a, 0.0f);
    }
    __syncthreads();

    const int wid = tid >> 5, lane = tid & 31;
    for (int c = wid; c < CC; c += 8) {
        const float* w2 = W2 + c * FCN;
        float a = 0.0f;
        #pragma unroll
        for (int q = 0; q < FCN / 32; q++) {
            int f = lane + 32 * q;
            a = fmaf(sF[f], w2[f], a);
        }
        #pragma unroll
        for (int off = 16; off; off >>= 1) a += __shfl_xor_sync(0xffffffffu, a, off);
        if (lane == 0) out[b * CC + c] = a + b2[c];
    }
}

extern "C" void kernel_launch(void* const* d_in, const int* in_sizes, int n_in,
                              void* d_out, int out_size)
{
    const float* x   = (const float*)d_in[0];
    const float* Wih = (const float*)d_in[1];
    const float* Whh = (const float*)d_in[2];
    const float* bih = (const float*)d_in[3];
    const float* bhh = (const float*)d_in[4];
    const float* Wp  = (const float*)d_in[5];
    const float* bp  = (const float*)d_in[6];
    const float* W1  = (const float*)d_in[7];
    const float* b1  = (const float*)d_in[8];
    const float* W2  = (const float*)d_in[9];
    const float* b2  = (const float*)d_in[10];
    float* out = (float*)d_out;

    cudaFuncSetAttribute(gru_kernel, cudaFuncAttributeMaxDynamicSharedMemorySize, SMEM_TOT);
    gru_kernel<<<VV * (BB / NB), NTHR, SMEM_TOT>>>(x, Wih, Whh, bih, bhh, Wp, bp);
    fc_kernel<<<BB, 256>>>(W1, b1, W2, b2, out);
}

// round 9
// speedup vs baseline: 4.3914x; 1.1787x over previous
#include <cuda_runtime.h>
#include <cuda_bf16.h>
#include <math.h>

#define VV 16
#define BB 64
#define TT 256
#define HH 128
#define GG 384
#define FCN 256
#define CC 10
#define NB 8            // batch rows per CTA = MMA N
#define NTHR 256        // 8 warps; warp w owns j-range [16w, 16w+16) for ALL 3 gates

// ---- smem byte offsets ----
#define OFF_WHI 0                        // W_hi bf16 [384][128] swizzled (reused as const table)
#define OFF_WLO (OFF_WHI + GG*256)       // 98304
#define OFF_H   (OFF_WLO + GG*256)       // 196608: h tiles, 2 parity bufs x (hi 4KB + lo 4KB)
#define OFF_X   (OFF_H + 4*4096)         // 212992: x f32 [8][256] (reused as hfin)
#define SMEM_TOT (OFF_X + NB*TT*4)       // 221184

typedef unsigned int u32;

__device__ float g_concat[BB * VV];

// XOR-swizzled byte offset within a [rows][128] bf16 tile (256B rows, 16B chunks)
__device__ __forceinline__ int swz(int r, int k) {
    return r * 256 + ((((k >> 3) ^ (r & 7)) & 15) << 4) + ((k & 7) << 1);
}

__device__ __forceinline__ u32 smem_u32(const void* p) {
    u32 a;
    asm("{ .reg .u64 t; cvta.to.shared.u64 t, %1; cvt.u32.u64 %0, t; }" : "=r"(a) : "l"(p));
    return a;
}

__device__ __forceinline__ void ldsm4(u32& a0, u32& a1, u32& a2, u32& a3, u32 addr) {
    asm volatile("ldmatrix.sync.aligned.m8n8.x4.shared.b16 {%0,%1,%2,%3}, [%4];"
                 : "=r"(a0), "=r"(a1), "=r"(a2), "=r"(a3) : "r"(addr));
}
__device__ __forceinline__ void mma16816(float* d, const u32* a, u32 b0, u32 b1) {
    asm volatile("mma.sync.aligned.m16n8k16.row.col.f32.bf16.bf16.f32 "
                 "{%0,%1,%2,%3}, {%4,%5,%6,%7}, {%8,%9}, {%0,%1,%2,%3};"
                 : "+f"(d[0]), "+f"(d[1]), "+f"(d[2]), "+f"(d[3])
                 : "r"(a[0]), "r"(a[1]), "r"(a[2]), "r"(a[3]), "r"(b0), "r"(b1));
}

__device__ __forceinline__ float tanha_(float x) {
    float y;
    asm("tanh.approx.f32 %0, %1;" : "=f"(y) : "f"(x));
    return y;
}
__device__ __forceinline__ float sigm_(float x) {
    return fmaf(0.5f, tanha_(0.5f * x), 0.5f);
}

__global__ __launch_bounds__(NTHR, 1)
void gru_kernel(const float* __restrict__ x,   const float* __restrict__ Wih,
                const float* __restrict__ Whh, const float* __restrict__ bih,
                const float* __restrict__ bhh, const float* __restrict__ Wp,
                const float* __restrict__ bp)
{
    extern __shared__ char sm[];
    const u32 smb = smem_u32(sm);
    const int tid = threadIdx.x;
    const int v  = blockIdx.x >> 3;          // 16 variables
    const int b0g = (blockIdx.x & 7) * NB;   // 8 batch-groups of 8

    // ---- stage Whh[v] as bf16 hi/lo into swizzled tiles ----
    const float* Whh_v = Whh + (size_t)v * GG * HH;
    for (int idx = tid; idx < GG * HH; idx += NTHR) {
        int g = idx >> 7, k = idx & 127;
        float wv = Whh_v[idx];
        __nv_bfloat16 hi = __float2bfloat16(wv);
        __nv_bfloat16 lo = __float2bfloat16(wv - __bfloat162float(hi));
        int o = swz(g, k);
        *(__nv_bfloat16*)(sm + OFF_WHI + o) = hi;
        *(__nv_bfloat16*)(sm + OFF_WLO + o) = lo;
    }
    // ---- zero h parity-buffer 0 (hi+lo); buffer 1 fully written at t=0 ----
    for (int idx = tid; idx < 8192 / 4; idx += NTHR)
        ((u32*)(sm + OFF_H))[idx] = 0u;
    // ---- stage x slice ----
    float* sXf = (float*)(sm + OFF_X);
    const float* x_v = x + (size_t)(v * BB + b0g) * TT;
    for (int idx = tid; idx < NB * TT; idx += NTHR) sXf[idx] = x_v[idx];

    // ---- lane geometry ----
    const int w = tid >> 5, L = tid & 31;
    const int rowl  = ((L >> 3) & 1) * 8 + (L & 7);  // A frag row within 16-tile
    const int khalf = (L >> 4) & 1;
    const int xr    = L & 7;
    // fused B ldsm4: lanes 0-15 -> h_hi, 16-31 -> h_lo
    const int nrow = L & 7;
    const int half = (L >> 3) & 1;
    const int losel = (L >> 4) & 1;
    const int quad = L >> 2, qc = L & 3;
    const int j0 = 16 * w + quad, j1 = j0 + 8;       // this lane's j rows
    const int c0 = 2 * qc, c1 = 2 * qc + 1;          // this lane's b cols

    __syncthreads();

    // ---- preload ALL A fragments (3 gates x 8 k-chunks x hi/lo) into registers ----
    u32 ar_h[8][4], az_h[8][4], an_h[8][4];
    u32 ar_l[8][4], az_l[8][4], an_l[8][4];
    {
        const u32 aR = smb + OFF_WHI + (u32)(16 * w + rowl) * 256;           // gate r
        const u32 aZ = aR + 128 * 256;                                        // gate z
        const u32 aN = aR + 256 * 256;                                        // gate n
        #pragma unroll
        for (int s = 0; s < 8; s++) {
            const u32 ca = (u32)((((2 * s + khalf) ^ xr) & 15) << 4);
            ldsm4(ar_h[s][0], ar_h[s][1], ar_h[s][2], ar_h[s][3], aR + ca);
            ldsm4(az_h[s][0], az_h[s][1], az_h[s][2], az_h[s][3], aZ + ca);
            ldsm4(an_h[s][0], an_h[s][1], an_h[s][2], an_h[s][3], aN + ca);
            ldsm4(ar_l[s][0], ar_l[s][1], ar_l[s][2], ar_l[s][3], aR + (OFF_WLO - OFF_WHI) + ca);
            ldsm4(az_l[s][0], az_l[s][1], az_l[s][2], az_l[s][3], aZ + (OFF_WLO - OFF_WHI) + ca);
            ldsm4(an_l[s][0], an_l[s][1], an_l[s][2], an_l[s][3], aN + (OFF_WLO - OFF_WHI) + ca);
        }
    }
    __syncthreads();

    // ---- gate constants (register-resident, 2 j values) via smem bounce ----
    float* sPC = (float*)(sm + OFF_WHI);   // reuse dead W_hi region
    if (tid < 128) {
        sPC[tid]       = Wih[v * GG + tid];
        sPC[128 + tid] = Wih[v * GG + 128 + tid];
        sPC[256 + tid] = Wih[v * GG + 256 + tid];
        sPC[384 + tid] = bih[v * GG + tid]       + bhh[v * GG + tid];
        sPC[512 + tid] = bih[v * GG + 128 + tid] + bhh[v * GG + 128 + tid];
        sPC[640 + tid] = bih[v * GG + 256 + tid];
        sPC[768 + tid] = bhh[v * GG + 256 + tid];
    }
    __syncthreads();
    const float wr0 = sPC[j0],      wr1 = sPC[j1];
    const float wz0 = sPC[128+j0],  wz1 = sPC[128+j1];
    const float wn0 = sPC[256+j0],  wn1 = sPC[256+j1];
    const float br0 = sPC[384+j0],  br1 = sPC[384+j1];
    const float bz0 = sPC[512+j0],  bz1 = sPC[512+j1];
    const float bi0 = sPC[640+j0],  bi1 = sPC[640+j1];
    const float bh0c = sPC[768+j0], bh1c = sPC[768+j1];

    const u32 bRd0 = smb + OFF_H + (u32)(losel * 4096) + (u32)nrow * 256;   // parity 0
    const u32 bRd1 = bRd0 + 8192;                                            // parity 1

    // lane's h elements: [0]=(j0,c0) [1]=(j0,c1) [2]=(j1,c0) [3]=(j1,c1)
    float hreg[4] = {0.f, 0.f, 0.f, 0.f};

    for (int t = 0; t < TT; t++) {
        const int p = t & 1;
        const u32 bRd = p ? bRd1 : bRd0;
        char* hw = sm + OFF_H + (p ^ 1) * 8192;

        // ============ MMA: acc{r,z,n} = Whi*hhi + Whi*hlo + Wlo*hhi ============
        float accr[4] = {0.f,0.f,0.f,0.f};
        float accz[4] = {0.f,0.f,0.f,0.f};
        float accn[4] = {0.f,0.f,0.f,0.f};
        u32 bh[2][2], bl[2][2];
        {
            const u32 cb = (u32)(((0 + half) ^ nrow & 15) << 4);  // s=0: chunk 0/1
            const u32 cb0 = (u32)((((0 + half) ^ nrow) & 15) << 4);
            ldsm4(bh[0][0], bh[0][1], bl[0][0], bl[0][1], bRd + cb0);
            (void)cb;
        }
        #pragma unroll
        for (int s = 0; s < 8; s++) {
            const int cu = s & 1, nx = cu ^ 1;
            if (s < 7) {
                const u32 cbn = (u32)((((2 * (s + 1) + half) ^ nrow) & 15) << 4);
                ldsm4(bh[nx][0], bh[nx][1], bl[nx][0], bl[nx][1], bRd + cbn);
            }
            mma16816(accr, ar_h[s], bh[cu][0], bh[cu][1]);
            mma16816(accz, az_h[s], bh[cu][0], bh[cu][1]);
            mma16816(accn, an_h[s], bh[cu][0], bh[cu][1]);
            mma16816(accr, ar_h[s], bl[cu][0], bl[cu][1]);
            mma16816(accz, az_h[s], bl[cu][0], bl[cu][1]);
            mma16816(accn, an_h[s], bl[cu][0], bl[cu][1]);
            mma16816(accr, ar_l[s], bh[cu][0], bh[cu][1]);
            mma16816(accz, az_l[s], bh[cu][0], bh[cu][1]);
            mma16816(accn, an_l[s], bh[cu][0], bh[cu][1]);
        }

        // ============ gates + state update, fully in-register ============
        const float xv0 = sXf[c0 * TT + t];
        const float xv1 = sXf[c1 * TT + t];
        #pragma unroll
        for (int i = 0; i < 4; i++) {
            const int jj = i >> 1;                 // 0 -> j0 consts, 1 -> j1
            const float xv = (i & 1) ? xv1 : xv0;
            const float wr = jj ? wr1 : wr0, wz = jj ? wz1 : wz0, wn = jj ? wn1 : wn0;
            const float br = jj ? br1 : br0, bz = jj ? bz1 : bz0;
            const float bi = jj ? bi1 : bi0, bh_ = jj ? bh1c : bh0c;
            float rg = sigm_(fmaf(xv, wr, br) + accr[i]);
            float zg = sigm_(fmaf(xv, wz, bz) + accz[i]);
            float ng = tanha_(fmaf(xv, wn, bi) + rg * (accn[i] + bh_));
            float hn = fmaf(zg, hreg[i] - ng, ng);          // (1-z)*n + z*h
            hreg[i] = hn;
            __nv_bfloat16 hi16 = __float2bfloat16(hn);
            __nv_bfloat16 lo16 = __float2bfloat16(hn - __bfloat162float(hi16));
            const int jx = jj ? j1 : j0;
            const int bx = (i & 1) ? c1 : c0;
            const int o = swz(bx, jx);
            *(__nv_bfloat16*)(hw + o)        = hi16;
            *(__nv_bfloat16*)(hw + 4096 + o) = lo16;
        }
        __syncthreads();
    }

    // ============ epilogue: concat[b][v] ============
    float* hfin = (float*)(sm + OFF_X);   // reuse x region: [8][128] f32
    hfin[c0 * HH + j0] = hreg[0];
    hfin[c1 * HH + j0] = hreg[1];
    hfin[c0 * HH + j1] = hreg[2];
    hfin[c1 * HH + j1] = hreg[3];
    __syncthreads();

    {
        const float* Wp_v = Wp + v * HH;
        float s = 0.0f;
        #pragma unroll
        for (int q = 0; q < 4; q++) {
            int jj = L + 32 * q;
            s = fmaf(hfin[w * HH + jj], Wp_v[jj], s);
        }
        #pragma unroll
        for (int off = 16; off; off >>= 1) s += __shfl_xor_sync(0xffffffffu, s, off);
        if (L == 0) g_concat[(b0g + w) * VV + v] = s + bp[v];
    }
}

// one CTA per batch row; warp-per-class output reduction
__global__ __launch_bounds__(256, 1)
void fc_kernel(const float* __restrict__ W1, const float* __restrict__ b1,
               const float* __restrict__ W2, const float* __restrict__ b2,
               float* __restrict__ out)
{
    __shared__ float sC[VV];
    __shared__ float sF[FCN];

    const int b = blockIdx.x;
    const int tid = threadIdx.x;

    if (tid < VV) sC[tid] = g_concat[b * VV + tid];
    __syncthreads();

    {
        float a = b1[tid];
        const float* w1 = W1 + tid * VV;
        #pragma unroll
        for (int vv = 0; vv < VV; vv++) a = fmaf(sC[vv], w1[vv], a);
        sF[tid] = fmaxf(a, 0.0f);
    }
    __syncthreads();

    const int wid = tid >> 5, lane = tid & 31;
    for (int c = wid; c < CC; c += 8) {
        const float* w2 = W2 + c * FCN;
        float a = 0.0f;
        #pragma unroll
        for (int q = 0; q < FCN / 32; q++) {
            int f = lane + 32 * q;
            a = fmaf(sF[f], w2[f], a);
        }
        #pragma unroll
        for (int off = 16; off; off >>= 1) a += __shfl_xor_sync(0xffffffffu, a, off);
        if (lane == 0) out[b * CC + c] = a + b2[c];
    }
}

extern "C" void kernel_launch(void* const* d_in, const int* in_sizes, int n_in,
                              void* d_out, int out_size)
{
    const float* x   = (const float*)d_in[0];
    const float* Wih = (const float*)d_in[1];
    const float* Whh = (const float*)d_in[2];
    const float* bih = (const float*)d_in[3];
    const float* bhh = (const float*)d_in[4];
    const float* Wp  = (const float*)d_in[5];
    const float* bp  = (const float*)d_in[6];
    const float* W1  = (const float*)d_in[7];
    const float* b1  = (const float*)d_in[8];
    const float* W2  = (const float*)d_in[9];
    const float* b2  = (const float*)d_in[10];
    float* out = (float*)d_out;

    cudaFuncSetAttribute(gru_kernel, cudaFuncAttributeMaxDynamicSharedMemorySize, SMEM_TOT);
    gru_kernel<<<VV * (BB / NB), NTHR, SMEM_TOT>>>(x, Wih, Whh, bih, bhh, Wp, bp);
    fc_kernel<<<BB, 256>>>(W1, b1, W2, b2, out);
}

// round 10
// speedup vs baseline: 5.8919x; 1.3417x over previous
#include <cuda_runtime.h>
#include <cuda_fp16.h>
#include <math.h>

#define VV 16
#define BB 64
#define TT 256
#define HH 128
#define GG 384
#define FCN 256
#define CC 10
#define NB 8            // batch rows per CTA = MMA N
#define NTHR 256        // 8 warps; warp w owns j-range [16w, 16w+16) for ALL 3 gates

// ---- smem byte offsets ----
#define OFF_WHI 0                        // W_hi fp16 [384][128] swizzled (reused as const table)
#define OFF_WLO (OFF_WHI + GG*256)       // 98304
#define OFF_H   (OFF_WLO + GG*256)       // 196608: h_q fp16 tiles, 2 parity bufs x 4KB
#define OFF_X   (OFF_H + 2*4096)         // 204800: x f32 [8][256] (reused as hfin)
#define SMEM_TOT (OFF_X + NB*TT*4)       // 212992

typedef unsigned int u32;

__device__ float g_concat[BB * VV];

// XOR-swizzled byte offset within a [rows][128] 16-bit tile (256B rows, 16B chunks)
__device__ __forceinline__ int swz(int r, int k) {
    return r * 256 + ((((k >> 3) ^ (r & 7)) & 15) << 4) + ((k & 7) << 1);
}

__device__ __forceinline__ u32 smem_u32(const void* p) {
    u32 a;
    asm("{ .reg .u64 t; cvta.to.shared.u64 t, %1; cvt.u32.u64 %0, t; }" : "=r"(a) : "l"(p));
    return a;
}

__device__ __forceinline__ void ldsm4(u32& a0, u32& a1, u32& a2, u32& a3, u32 addr) {
    asm volatile("ldmatrix.sync.aligned.m8n8.x4.shared.b16 {%0,%1,%2,%3}, [%4];"
                 : "=r"(a0), "=r"(a1), "=r"(a2), "=r"(a3) : "r"(addr));
}
__device__ __forceinline__ void mma16816(float* d, const u32* a, u32 b0, u32 b1) {
    asm volatile("mma.sync.aligned.m16n8k16.row.col.f32.f16.f16.f32 "
                 "{%0,%1,%2,%3}, {%4,%5,%6,%7}, {%8,%9}, {%0,%1,%2,%3};"
                 : "+f"(d[0]), "+f"(d[1]), "+f"(d[2]), "+f"(d[3])
                 : "r"(a[0]), "r"(a[1]), "r"(a[2]), "r"(a[3]), "r"(b0), "r"(b1));
}

__device__ __forceinline__ float tanha_(float x) {
    float y;
    asm("tanh.approx.f32 %0, %1;" : "=f"(y) : "f"(x));
    return y;
}
__device__ __forceinline__ float sigm_(float x) {
    return fmaf(0.5f, tanha_(0.5f * x), 0.5f);
}

__global__ __launch_bounds__(NTHR, 1)
void gru_kernel(const float* __restrict__ x,   const float* __restrict__ Wih,
                const float* __restrict__ Whh, const float* __restrict__ bih,
                const float* __restrict__ bhh, const float* __restrict__ Wp,
                const float* __restrict__ bp)
{
    extern __shared__ char sm[];
    const u32 smb = smem_u32(sm);
    const int tid = threadIdx.x;
    const int v  = blockIdx.x >> 3;          // 16 variables
    const int b0g = (blockIdx.x & 7) * NB;   // 8 batch-groups of 8

    // ---- stage Whh[v] as fp16 hi/lo into swizzled tiles (exact 2-term split) ----
    const float* Whh_v = Whh + (size_t)v * GG * HH;
    for (int idx = tid; idx < GG * HH; idx += NTHR) {
        int g = idx >> 7, k = idx & 127;
        float wv = Whh_v[idx];
        __half hi = __float2half_rn(wv);
        __half lo = __float2half_rn(wv - __half2float(hi));
        int o = swz(g, k);
        *(__half*)(sm + OFF_WHI + o) = hi;
        *(__half*)(sm + OFF_WLO + o) = lo;
    }
    // ---- zero h parity-buffer 0; buffer 1 fully written at t=0 ----
    for (int idx = tid; idx < 4096 / 4; idx += NTHR)
        ((u32*)(sm + OFF_H))[idx] = 0u;
    // ---- stage x slice ----
    float* sXf = (float*)(sm + OFF_X);
    const float* x_v = x + (size_t)(v * BB + b0g) * TT;
    for (int idx = tid; idx < NB * TT; idx += NTHR) sXf[idx] = x_v[idx];

    // ---- lane geometry ----
    const int w = tid >> 5, L = tid & 31;
    const int rowl  = ((L >> 3) & 1) * 8 + (L & 7);  // A frag row within 16-tile
    const int khalf = (L >> 4) & 1;
    const int xr    = L & 7;
    // B ldsm4: lane group g=L>>3 (0..3) fetches k-chunk 4*sp+g of the h_q tile
    const int nrow = L & 7;
    const int bg   = (L >> 3) & 3;
    const int quad = L >> 2, qc = L & 3;
    const int j0 = 16 * w + quad, j1 = j0 + 8;       // this lane's j rows
    const int c0 = 2 * qc, c1 = 2 * qc + 1;          // this lane's b cols

    __syncthreads();

    // ---- preload ALL A fragments (3 gates x 8 k-chunks x hi/lo) into registers ----
    u32 ar_h[8][4], az_h[8][4], an_h[8][4];
    u32 ar_l[8][4], az_l[8][4], an_l[8][4];
    {
        const u32 aR = smb + OFF_WHI + (u32)(16 * w + rowl) * 256;           // gate r
        const u32 aZ = aR + 128 * 256;                                        // gate z
        const u32 aN = aR + 256 * 256;                                        // gate n
        #pragma unroll
        for (int s = 0; s < 8; s++) {
            const u32 ca = (u32)((((2 * s + khalf) ^ xr) & 15) << 4);
            ldsm4(ar_h[s][0], ar_h[s][1], ar_h[s][2], ar_h[s][3], aR + ca);
            ldsm4(az_h[s][0], az_h[s][1], az_h[s][2], az_h[s][3], aZ + ca);
            ldsm4(an_h[s][0], an_h[s][1], an_h[s][2], an_h[s][3], aN + ca);
            ldsm4(ar_l[s][0], ar_l[s][1], ar_l[s][2], ar_l[s][3], aR + (OFF_WLO - OFF_WHI) + ca);
            ldsm4(az_l[s][0], az_l[s][1], az_l[s][2], az_l[s][3], aZ + (OFF_WLO - OFF_WHI) + ca);
            ldsm4(an_l[s][0], an_l[s][1], an_l[s][2], an_l[s][3], aN + (OFF_WLO - OFF_WHI) + ca);
        }
    }
    __syncthreads();

    // ---- gate constants (register-resident, 2 j values) via smem bounce ----
    float* sPC = (float*)(sm + OFF_WHI);   // reuse dead W_hi region
    if (tid < 128) {
        sPC[tid]       = Wih[v * GG + tid];
        sPC[128 + tid] = Wih[v * GG + 128 + tid];
        sPC[256 + tid] = Wih[v * GG + 256 + tid];
        sPC[384 + tid] = bih[v * GG + tid]       + bhh[v * GG + tid];
        sPC[512 + tid] = bih[v * GG + 128 + tid] + bhh[v * GG + 128 + tid];
        sPC[640 + tid] = bih[v * GG + 256 + tid];
        sPC[768 + tid] = bhh[v * GG + 256 + tid];
    }
    __syncthreads();
    const float wr0 = sPC[j0],      wr1 = sPC[j1];
    const float wz0 = sPC[128+j0],  wz1 = sPC[128+j1];
    const float wn0 = sPC[256+j0],  wn1 = sPC[256+j1];
    const float br0 = sPC[384+j0],  br1 = sPC[384+j1];
    const float bz0 = sPC[512+j0],  bz1 = sPC[512+j1];
    const float bi0 = sPC[640+j0],  bi1 = sPC[640+j1];
    const float bh0c = sPC[768+j0], bh1c = sPC[768+j1];

    const u32 bRd0 = smb + OFF_H + (u32)nrow * 256;    // parity 0
    const u32 bRd1 = bRd0 + 4096;                      // parity 1

    // per-sp chunk-select offsets: lane group bg fetches chunk 4*sp+bg
    u32 cbo[4];
    #pragma unroll
    for (int sp = 0; sp < 4; sp++)
        cbo[sp] = (u32)((((4 * sp + bg) ^ nrow) & 15) << 4);

    // lane's h elements: [0]=(j0,c0) [1]=(j0,c1) [2]=(j1,c0) [3]=(j1,c1)
    float hreg[4] = {0.f, 0.f, 0.f, 0.f};

    for (int t = 0; t < TT; t++) {
        const int p = t & 1;
        const u32 bRd = p ? bRd1 : bRd0;
        char* hw = sm + OFF_H + (p ^ 1) * 4096;

        // ============ MMA: acc{r,z,n} = (Whi + Wlo) * h_q  (2-term fp16) ============
        float accr[4] = {0.f,0.f,0.f,0.f};
        float accz[4] = {0.f,0.f,0.f,0.f};
        float accn[4] = {0.f,0.f,0.f,0.f};
        u32 bq[2][4];
        ldsm4(bq[0][0], bq[0][1], bq[0][2], bq[0][3], bRd + cbo[0]);
        #pragma unroll
        for (int sp = 0; sp < 4; sp++) {
            const int cu = sp & 1, nx = cu ^ 1;
            if (sp < 3) ldsm4(bq[nx][0], bq[nx][1], bq[nx][2], bq[nx][3], bRd + cbo[sp + 1]);
            const int s0 = 2 * sp, s1 = 2 * sp + 1;
            mma16816(accr, ar_h[s0], bq[cu][0], bq[cu][1]);
            mma16816(accz, az_h[s0], bq[cu][0], bq[cu][1]);
            mma16816(accn, an_h[s0], bq[cu][0], bq[cu][1]);
            mma16816(accr, ar_l[s0], bq[cu][0], bq[cu][1]);
            mma16816(accz, az_l[s0], bq[cu][0], bq[cu][1]);
            mma16816(accn, an_l[s0], bq[cu][0], bq[cu][1]);
            mma16816(accr, ar_h[s1], bq[cu][2], bq[cu][3]);
            mma16816(accz, az_h[s1], bq[cu][2], bq[cu][3]);
            mma16816(accn, an_h[s1], bq[cu][2], bq[cu][3]);
            mma16816(accr, ar_l[s1], bq[cu][2], bq[cu][3]);
            mma16816(accz, az_l[s1], bq[cu][2], bq[cu][3]);
            mma16816(accn, an_l[s1], bq[cu][2], bq[cu][3]);
        }

        // ============ gates + state update, fully in-register ============
        const float xv0 = sXf[c0 * TT + t];
        const float xv1 = sXf[c1 * TT + t];
        #pragma unroll
        for (int i = 0; i < 4; i++) {
            const int jj = i >> 1;                 // 0 -> j0 consts, 1 -> j1
            const float xv = (i & 1) ? xv1 : xv0;
            const float wr = jj ? wr1 : wr0, wz = jj ? wz1 : wz0, wn = jj ? wn1 : wn0;
            const float br = jj ? br1 : br0, bz = jj ? bz1 : bz0;
            const float bi = jj ? bi1 : bi0, bh_ = jj ? bh1c : bh0c;
            float rg = sigm_(fmaf(xv, wr, br) + accr[i]);
            float zg = sigm_(fmaf(xv, wz, bz) + accz[i]);
            float ng = tanha_(fmaf(xv, wn, bi) + rg * (accn[i] + bh_));
            float hn = fmaf(zg, hreg[i] - ng, ng);          // (1-z)*n + z*h
            hreg[i] = hn;
            const int jx = jj ? j1 : j0;
            const int bx = (i & 1) ? c1 : c0;
            *(__half*)(hw + swz(bx, jx)) = __float2half_rn(hn);
        }
        __syncthreads();
    }

    // ============ epilogue: concat[b][v] ============
    float* hfin = (float*)(sm + OFF_X);   // reuse x region: [8][128] f32
    hfin[c0 * HH + j0] = hreg[0];
    hfin[c1 * HH + j0] = hreg[1];
    hfin[c0 * HH + j1] = hreg[2];
    hfin[c1 * HH + j1] = hreg[3];
    __syncthreads();

    {
        const float* Wp_v = Wp + v * HH;
        float s = 0.0f;
        #pragma unroll
        for (int q = 0; q < 4; q++) {
            int jj = L + 32 * q;
            s = fmaf(hfin[w * HH + jj], Wp_v[jj], s);
        }
        #pragma unroll
        for (int off = 16; off; off >>= 1) s += __shfl_xor_sync(0xffffffffu, s, off);
        if (L == 0) g_concat[(b0g + w) * VV + v] = s + bp[v];
    }
}

// one CTA per batch row; warp-per-class output reduction
__global__ __launch_bounds__(256, 1)
void fc_kernel(const float* __restrict__ W1, const float* __restrict__ b1,
               const float* __restrict__ W2, const float* __restrict__ b2,
               float* __restrict__ out)
{
    __shared__ float sC[VV];
    __shared__ float sF[FCN];

    const int b = blockIdx.x;
    const int tid = threadIdx.x;

    if (tid < VV) sC[tid] = g_concat[b * VV + tid];
    __syncthreads();

    {
        float a = b1[tid];
        const float* w1 = W1 + tid * VV;
        #pragma unroll
        for (int vv = 0; vv < VV; vv++) a = fmaf(sC[vv], w1[vv], a);
        sF[tid] = fmaxf(a, 0.0f);
    }
    __syncthreads();

    const int wid = tid >> 5, lane = tid & 31;
    for (int c = wid; c < CC; c += 8) {
        const float* w2 = W2 + c * FCN;
        float a = 0.0f;
        #pragma unroll
        for (int q = 0; q < FCN / 32; q++) {
            int f = lane + 32 * q;
            a = fmaf(sF[f], w2[f], a);
        }
        #pragma unroll
        for (int off = 16; off; off >>= 1) a += __shfl_xor_sync(0xffffffffu, a, off);
        if (lane == 0) out[b * CC + c] = a + b2[c];
    }
}

extern "C" void kernel_launch(void* const* d_in, const int* in_sizes, int n_in,
                              void* d_out, int out_size)
{
    const float* x   = (const float*)d_in[0];
    const float* Wih = (const float*)d_in[1];
    const float* Whh = (const float*)d_in[2];
    const float* bih = (const float*)d_in[3];
    const float* bhh = (const float*)d_in[4];
    const float* Wp  = (const float*)d_in[5];
    const float* bp  = (const float*)d_in[6];
    const float* W1  = (const float*)d_in[7];
    const float* b1  = (const float*)d_in[8];
    const float* W2  = (const float*)d_in[9];
    const float* b2  = (const float*)d_in[10];
    float* out = (float*)d_out;

    cudaFuncSetAttribute(gru_kernel, cudaFuncAttributeMaxDynamicSharedMemorySize, SMEM_TOT);
    gru_kernel<<<VV * (BB / NB), NTHR, SMEM_TOT>>>(x, Wih, Whh, bih, bhh, Wp, bp);
    fc_kernel<<<BB, 256>>>(W1, b1, W2, b2, out);
}

// round 11
// speedup vs baseline: 7.4226x; 1.2598x over previous
#include <cuda_runtime.h>
#include <cuda_fp16.h>
#include <math.h>

#define VV 16
#define BB 64
#define TT 256
#define HH 128
#define GG 384
#define FCN 256
#define CC 10
#define NB 8            // batch rows per CTA = MMA N
#define NTHR 256        // 8 warps; warp w owns j-range [16w, 16w+16) for ALL 3 gates

// ---- smem byte offsets ----
#define OFF_WHI 0                        // W_hi fp16 [384][128] swizzled (reused as const table)
#define OFF_WLO (OFF_WHI + GG*256)       // 98304 (only gate-n rows used in loop)
#define OFF_H   (OFF_WLO + GG*256)       // 196608: h_q fp16 tiles, 2 parity bufs x 4KB
#define OFF_X   (OFF_H + 2*4096)         // 204800: x f32 [8][256] (reused as hfin)
#define SMEM_TOT (OFF_X + NB*TT*4)       // 212992

typedef unsigned int u32;

__device__ float g_concat[BB * VV];

// XOR-swizzled byte offset within a [rows][128] 16-bit tile (256B rows, 16B chunks)
__device__ __forceinline__ int swz(int r, int k) {
    return r * 256 + ((((k >> 3) ^ (r & 7)) & 15) << 4) + ((k & 7) << 1);
}

__device__ __forceinline__ u32 smem_u32(const void* p) {
    u32 a;
    asm("{ .reg .u64 t; cvta.to.shared.u64 t, %1; cvt.u32.u64 %0, t; }" : "=r"(a) : "l"(p));
    return a;
}

__device__ __forceinline__ void ldsm4(u32& a0, u32& a1, u32& a2, u32& a3, u32 addr) {
    asm volatile("ldmatrix.sync.aligned.m8n8.x4.shared.b16 {%0,%1,%2,%3}, [%4];"
                 : "=r"(a0), "=r"(a1), "=r"(a2), "=r"(a3) : "r"(addr));
}
__device__ __forceinline__ void mma16816(float* d, const u32* a, u32 b0, u32 b1) {
    asm volatile("mma.sync.aligned.m16n8k16.row.col.f32.f16.f16.f32 "
                 "{%0,%1,%2,%3}, {%4,%5,%6,%7}, {%8,%9}, {%0,%1,%2,%3};"
                 : "+f"(d[0]), "+f"(d[1]), "+f"(d[2]), "+f"(d[3])
                 : "r"(a[0]), "r"(a[1]), "r"(a[2]), "r"(a[3]), "r"(b0), "r"(b1));
}

__device__ __forceinline__ float tanha_(float x) {
    float y;
    asm("tanh.approx.f32 %0, %1;" : "=f"(y) : "f"(x));
    return y;
}
__device__ __forceinline__ float sigm_(float x) {
    return fmaf(0.5f, tanha_(0.5f * x), 0.5f);
}

__global__ __launch_bounds__(NTHR, 1)
void gru_kernel(const float* __restrict__ x,   const float* __restrict__ Wih,
                const float* __restrict__ Whh, const float* __restrict__ bih,
                const float* __restrict__ bhh, const float* __restrict__ Wp,
                const float* __restrict__ bp)
{
    extern __shared__ char sm[];
    const u32 smb = smem_u32(sm);
    const int tid = threadIdx.x;
    const int v  = blockIdx.x >> 3;          // 16 variables
    const int b0g = (blockIdx.x & 7) * NB;   // 8 batch-groups of 8

    // ---- stage Whh[v] as fp16 hi/lo into swizzled tiles (exact 2-term split) ----
    const float* Whh_v = Whh + (size_t)v * GG * HH;
    for (int idx = tid; idx < GG * HH; idx += NTHR) {
        int g = idx >> 7, k = idx & 127;
        float wv = Whh_v[idx];
        __half hi = __float2half_rn(wv);
        __half lo = __float2half_rn(wv - __half2float(hi));
        int o = swz(g, k);
        *(__half*)(sm + OFF_WHI + o) = hi;
        *(__half*)(sm + OFF_WLO + o) = lo;
    }
    // ---- zero h parity-buffer 0; buffer 1 fully written at t=0 ----
    for (int idx = tid; idx < 4096 / 4; idx += NTHR)
        ((u32*)(sm + OFF_H))[idx] = 0u;
    // ---- stage x slice ----
    float* sXf = (float*)(sm + OFF_X);
    const float* x_v = x + (size_t)(v * BB + b0g) * TT;
    for (int idx = tid; idx < NB * TT; idx += NTHR) sXf[idx] = x_v[idx];

    // ---- lane geometry ----
    const int w = tid >> 5, L = tid & 31;
    const int rowl  = ((L >> 3) & 1) * 8 + (L & 7);  // A frag row within 16-tile
    const int khalf = (L >> 4) & 1;
    const int xr    = L & 7;
    // B ldsm4: lane group bg (0..3) fetches k-chunk 4*sp+bg of the h_q tile
    const int nrow = L & 7;
    const int bg   = (L >> 3) & 3;
    const int quad = L >> 2, qc = L & 3;
    const int j0 = 16 * w + quad, j1 = j0 + 8;       // this lane's j rows
    const int c0 = 2 * qc, c1 = 2 * qc + 1;          // this lane's b cols

    __syncthreads();

    // ---- preload A fragments: r/z hi only; n hi+lo (gate-selective precision) ----
    u32 ar_h[8][4], az_h[8][4], an_h[8][4], an_l[8][4];
    {
        const u32 aR = smb + OFF_WHI + (u32)(16 * w + rowl) * 256;           // gate r
        const u32 aZ = aR + 128 * 256;                                        // gate z
        const u32 aN = aR + 256 * 256;                                        // gate n
        #pragma unroll
        for (int s = 0; s < 8; s++) {
            const u32 ca = (u32)((((2 * s + khalf) ^ xr) & 15) << 4);
            ldsm4(ar_h[s][0], ar_h[s][1], ar_h[s][2], ar_h[s][3], aR + ca);
            ldsm4(az_h[s][0], az_h[s][1], az_h[s][2], az_h[s][3], aZ + ca);
            ldsm4(an_h[s][0], an_h[s][1], an_h[s][2], an_h[s][3], aN + ca);
            ldsm4(an_l[s][0], an_l[s][1], an_l[s][2], an_l[s][3], aN + (OFF_WLO - OFF_WHI) + ca);
        }
    }
    __syncthreads();

    // ---- gate constants (register-resident, 2 j values) via smem bounce ----
    float* sPC = (float*)(sm + OFF_WHI);   // reuse dead W_hi region
    if (tid < 128) {
        sPC[tid]       = Wih[v * GG + tid];
        sPC[128 + tid] = Wih[v * GG + 128 + tid];
        sPC[256 + tid] = Wih[v * GG + 256 + tid];
        sPC[384 + tid] = bih[v * GG + tid]       + bhh[v * GG + tid];
        sPC[512 + tid] = bih[v * GG + 128 + tid] + bhh[v * GG + 128 + tid];
        sPC[640 + tid] = bih[v * GG + 256 + tid];
        sPC[768 + tid] = bhh[v * GG + 256 + tid];
    }
    __syncthreads();
    const float wr0 = sPC[j0],      wr1 = sPC[j1];
    const float wz0 = sPC[128+j0],  wz1 = sPC[128+j1];
    const float wn0 = sPC[256+j0],  wn1 = sPC[256+j1];
    const float br0 = sPC[384+j0],  br1 = sPC[384+j1];
    const float bz0 = sPC[512+j0],  bz1 = sPC[512+j1];
    const float bi0 = sPC[640+j0],  bi1 = sPC[640+j1];
    const float bh0c = sPC[768+j0], bh1c = sPC[768+j1];

    const u32 bRd0 = smb + OFF_H + (u32)nrow * 256;    // parity 0
    const u32 bRd1 = bRd0 + 4096;                      // parity 1

    // per-sp chunk-select offsets: lane group bg fetches chunk 4*sp+bg
    u32 cbo[4];
    #pragma unroll
    for (int sp = 0; sp < 4; sp++)
        cbo[sp] = (u32)((((4 * sp + bg) ^ nrow) & 15) << 4);

    // lane's h elements: [0]=(j0,c0) [1]=(j0,c1) [2]=(j1,c0) [3]=(j1,c1)
    float hreg[4] = {0.f, 0.f, 0.f, 0.f};

    for (int t = 0; t < TT; t++) {
        const int p = t & 1;
        const u32 bRd = p ? bRd1 : bRd0;
        char* hw = sm + OFF_H + (p ^ 1) * 4096;

        // ==== MMA: r,z = Whi*h_q (1 term);  n = (Whi+Wlo)*h_q (2 terms) ====
        float accr[4] = {0.f,0.f,0.f,0.f};
        float accz[4] = {0.f,0.f,0.f,0.f};
        float accn[4] = {0.f,0.f,0.f,0.f};
        u32 bq[2][4];
        ldsm4(bq[0][0], bq[0][1], bq[0][2], bq[0][3], bRd + cbo[0]);
        #pragma unroll
        for (int sp = 0; sp < 4; sp++) {
            const int cu = sp & 1, nx = cu ^ 1;
            if (sp < 3) ldsm4(bq[nx][0], bq[nx][1], bq[nx][2], bq[nx][3], bRd + cbo[sp + 1]);
            const int s0 = 2 * sp, s1 = 2 * sp + 1;
            mma16816(accr, ar_h[s0], bq[cu][0], bq[cu][1]);
            mma16816(accz, az_h[s0], bq[cu][0], bq[cu][1]);
            mma16816(accn, an_h[s0], bq[cu][0], bq[cu][1]);
            mma16816(accn, an_l[s0], bq[cu][0], bq[cu][1]);
            mma16816(accr, ar_h[s1], bq[cu][2], bq[cu][3]);
            mma16816(accz, az_h[s1], bq[cu][2], bq[cu][3]);
            mma16816(accn, an_h[s1], bq[cu][2], bq[cu][3]);
            mma16816(accn, an_l[s1], bq[cu][2], bq[cu][3]);
        }

        // ============ gates + state update, fully in-register ============
        const float xv0 = sXf[c0 * TT + t];
        const float xv1 = sXf[c1 * TT + t];
        #pragma unroll
        for (int i = 0; i < 4; i++) {
            const int jj = i >> 1;                 // 0 -> j0 consts, 1 -> j1
            const float xv = (i & 1) ? xv1 : xv0;
            const float wr = jj ? wr1 : wr0, wz = jj ? wz1 : wz0, wn = jj ? wn1 : wn0;
            const float br = jj ? br1 : br0, bz = jj ? bz1 : bz0;
            const float bi = jj ? bi1 : bi0, bh_ = jj ? bh1c : bh0c;
            float rg = sigm_(fmaf(xv, wr, br) + accr[i]);
            float zg = sigm_(fmaf(xv, wz, bz) + accz[i]);
            float ng = tanha_(fmaf(xv, wn, bi) + rg * (accn[i] + bh_));
            float hn = fmaf(zg, hreg[i] - ng, ng);          // (1-z)*n + z*h
            hreg[i] = hn;
            const int jx = jj ? j1 : j0;
            const int bx = (i & 1) ? c1 : c0;
            *(__half*)(hw + swz(bx, jx)) = __float2half_rn(hn);
        }
        __syncthreads();
    }

    // ============ epilogue: concat[b][v] ============
    float* hfin = (float*)(sm + OFF_X);   // reuse x region: [8][128] f32
    hfin[c0 * HH + j0] = hreg[0];
    hfin[c1 * HH + j0] = hreg[1];
    hfin[c0 * HH + j1] = hreg[2];
    hfin[c1 * HH + j1] = hreg[3];
    __syncthreads();

    {
        const float* Wp_v = Wp + v * HH;
        float s = 0.0f;
        #pragma unroll
        for (int q = 0; q < 4; q++) {
            int jj = L + 32 * q;
            s = fmaf(hfin[w * HH + jj], Wp_v[jj], s);
        }
        #pragma unroll
        for (int off = 16; off; off >>= 1) s += __shfl_xor_sync(0xffffffffu, s, off);
        if (L == 0) g_concat[(b0g + w) * VV + v] = s + bp[v];
    }
}

// one CTA per batch row; warp-per-class output reduction
__global__ __launch_bounds__(256, 1)
void fc_kernel(const float* __restrict__ W1, const float* __restrict__ b1,
               const float* __restrict__ W2, const float* __restrict__ b2,
               float* __restrict__ out)
{
    __shared__ float sC[VV];
    __shared__ float sF[FCN];

    const int b = blockIdx.x;
    const int tid = threadIdx.x;

    if (tid < VV) sC[tid] = g_concat[b * VV + tid];
    __syncthreads();

    {
        float a = b1[tid];
        const float* w1 = W1 + tid * VV;
        #pragma unroll
        for (int vv = 0; vv < VV; vv++) a = fmaf(sC[vv], w1[vv], a);
        sF[tid] = fmaxf(a, 0.0f);
    }
    __syncthreads();

    const int wid = tid >> 5, lane = tid & 31;
    for (int c = wid; c < CC; c += 8) {
        const float* w2 = W2 + c * FCN;
        float a = 0.0f;
        #pragma unroll
        for (int q = 0; q < FCN / 32; q++) {
            int f = lane + 32 * q;
            a = fmaf(sF[f], w2[f], a);
        }
        #pragma unroll
        for (int off = 16; off; off >>= 1) a += __shfl_xor_sync(0xffffffffu, a, off);
        if (lane == 0) out[b * CC + c] = a + b2[c];
    }
}

extern "C" void kernel_launch(void* const* d_in, const int* in_sizes, int n_in,
                              void* d_out, int out_size)
{
    const float* x   = (const float*)d_in[0];
    const float* Wih = (const float*)d_in[1];
    const float* Whh = (const float*)d_in[2];
    const float* bih = (const float*)d_in[3];
    const float* bhh = (const float*)d_in[4];
    const float* Wp  = (const float*)d_in[5];
    const float* bp  = (const float*)d_in[6];
    const float* W1  = (const float*)d_in[7];
    const float* b1  = (const float*)d_in[8];
    const float* W2  = (const float*)d_in[9];
    const float* b2  = (const float*)d_in[10];
    float* out = (float*)d_out;

    cudaFuncSetAttribute(gru_kernel, cudaFuncAttributeMaxDynamicSharedMemorySize, SMEM_TOT);
    gru_kernel<<<VV * (BB / NB), NTHR, SMEM_TOT>>>(x, Wih, Whh, bih, bhh, Wp, bp);
    fc_kernel<<<BB, 256>>>(W1, b1, W2, b2, out);
}

// round 12
// speedup vs baseline: 8.4852x; 1.1432x over previous
#include <cuda_runtime.h>
#include <cuda_fp16.h>
#include <math.h>

#define VV 16
#define BB 64
#define TT 256
#define HH 128
#define GG 384
#define FCN 256
#define CC 10
#define NB 8            // batch rows per CTA = MMA N
#define NTHR 256        // 8 warps; warp w owns j-range [16w, 16w+16) for ALL 3 gates

// ---- smem byte offsets ----
#define OFF_WHI 0                        // W_hi fp16 [384][128] swizzled (reused as const table)
#define OFF_H   (OFF_WHI + GG*256)       // 98304: h_q fp16 tiles, 2 parity bufs x 4KB
#define OFF_X   (OFF_H + 2*4096)         // 106496: x f32 [8][256] (reused as hfin)
#define SMEM_TOT (OFF_X + NB*TT*4)       // 114688

typedef unsigned int u32;

__device__ float g_concat[BB * VV];

// XOR-swizzled byte offset within a [rows][128] 16-bit tile (256B rows, 16B chunks)
__device__ __forceinline__ int swz(int r, int k) {
    return r * 256 + ((((k >> 3) ^ (r & 7)) & 15) << 4) + ((k & 7) << 1);
}

__device__ __forceinline__ u32 smem_u32(const void* p) {
    u32 a;
    asm("{ .reg .u64 t; cvta.to.shared.u64 t, %1; cvt.u32.u64 %0, t; }" : "=r"(a) : "l"(p));
    return a;
}

__device__ __forceinline__ void ldsm4(u32& a0, u32& a1, u32& a2, u32& a3, u32 addr) {
    asm volatile("ldmatrix.sync.aligned.m8n8.x4.shared.b16 {%0,%1,%2,%3}, [%4];"
                 : "=r"(a0), "=r"(a1), "=r"(a2), "=r"(a3) : "r"(addr));
}
__device__ __forceinline__ void mma16816(float* d, const u32* a, u32 b0, u32 b1) {
    asm volatile("mma.sync.aligned.m16n8k16.row.col.f32.f16.f16.f32 "
                 "{%0,%1,%2,%3}, {%4,%5,%6,%7}, {%8,%9}, {%0,%1,%2,%3};"
                 : "+f"(d[0]), "+f"(d[1]), "+f"(d[2]), "+f"(d[3])
                 : "r"(a[0]), "r"(a[1]), "r"(a[2]), "r"(a[3]), "r"(b0), "r"(b1));
}

__device__ __forceinline__ float tanha_(float x) {
    float y;
    asm("tanh.approx.f32 %0, %1;" : "=f"(y) : "f"(x));
    return y;
}
__device__ __forceinline__ float sigm_(float x) {
    return fmaf(0.5f, tanha_(0.5f * x), 0.5f);
}

__global__ __launch_bounds__(NTHR, 1)
void gru_kernel(const float* __restrict__ x,   const float* __restrict__ Wih,
                const float* __restrict__ Whh, const float* __restrict__ bih,
                const float* __restrict__ bhh, const float* __restrict__ Wp,
                const float* __restrict__ bp)
{
    extern __shared__ char sm[];
    const u32 smb = smem_u32(sm);
    const int tid = threadIdx.x;
    const int v  = blockIdx.x >> 3;          // 16 variables
    const int b0g = (blockIdx.x & 7) * NB;   // 8 batch-groups of 8

    // ---- stage Whh[v] as fp16 into swizzled tile ----
    const float* Whh_v = Whh + (size_t)v * GG * HH;
    for (int idx = tid; idx < GG * HH; idx += NTHR) {
        int g = idx >> 7, k = idx & 127;
        *(__half*)(sm + OFF_WHI + swz(g, k)) = __float2half_rn(Whh_v[idx]);
    }
    // ---- zero h parity-buffer 0; buffer 1 fully written at t=0 ----
    for (int idx = tid; idx < 4096 / 4; idx += NTHR)
        ((u32*)(sm + OFF_H))[idx] = 0u;
    // ---- stage x slice ----
    float* sXf = (float*)(sm + OFF_X);
    const float* x_v = x + (size_t)(v * BB + b0g) * TT;
    for (int idx = tid; idx < NB * TT; idx += NTHR) sXf[idx] = x_v[idx];

    // ---- lane geometry ----
    const int w = tid >> 5, L = tid & 31;
    const int rowl  = ((L >> 3) & 1) * 8 + (L & 7);  // A frag row within 16-tile
    const int khalf = (L >> 4) & 1;
    const int xr    = L & 7;
    // B ldsm4: lane group bg (0..3) fetches k-chunk 4*sp+bg of the h_q tile
    const int nrow = L & 7;
    const int bg   = (L >> 3) & 3;
    const int quad = L >> 2, qc = L & 3;
    const int j0 = 16 * w + quad, j1 = j0 + 8;       // this lane's j rows
    const int c0 = 2 * qc, c1 = 2 * qc + 1;          // this lane's b cols

    __syncthreads();

    // ---- preload A fragments: all 3 gates, W_hi only (1-term fp16) ----
    u32 ar_h[8][4], az_h[8][4], an_h[8][4];
    {
        const u32 aR = smb + OFF_WHI + (u32)(16 * w + rowl) * 256;           // gate r
        const u32 aZ = aR + 128 * 256;                                        // gate z
        const u32 aN = aR + 256 * 256;                                        // gate n
        #pragma unroll
        for (int s = 0; s < 8; s++) {
            const u32 ca = (u32)((((2 * s + khalf) ^ xr) & 15) << 4);
            ldsm4(ar_h[s][0], ar_h[s][1], ar_h[s][2], ar_h[s][3], aR + ca);
            ldsm4(az_h[s][0], az_h[s][1], az_h[s][2], az_h[s][3], aZ + ca);
            ldsm4(an_h[s][0], an_h[s][1], an_h[s][2], an_h[s][3], aN + ca);
        }
    }
    __syncthreads();

    // ---- gate constants (register-resident, 2 j values) via smem bounce ----
    float* sPC = (float*)(sm + OFF_WHI);   // reuse dead W region
    if (tid < 128) {
        sPC[tid]       = Wih[v * GG + tid];
        sPC[128 + tid] = Wih[v * GG + 128 + tid];
        sPC[256 + tid] = Wih[v * GG + 256 + tid];
        sPC[384 + tid] = bih[v * GG + tid]       + bhh[v * GG + tid];
        sPC[512 + tid] = bih[v * GG + 128 + tid] + bhh[v * GG + 128 + tid];
        sPC[640 + tid] = bih[v * GG + 256 + tid];
        sPC[768 + tid] = bhh[v * GG + 256 + tid];
    }
    __syncthreads();
    const float wr0 = sPC[j0],      wr1 = sPC[j1];
    const float wz0 = sPC[128+j0],  wz1 = sPC[128+j1];
    const float wn0 = sPC[256+j0],  wn1 = sPC[256+j1];
    const float br0 = sPC[384+j0],  br1 = sPC[384+j1];
    const float bz0 = sPC[512+j0],  bz1 = sPC[512+j1];
    const float bi0 = sPC[640+j0],  bi1 = sPC[640+j1];
    const float bh0c = sPC[768+j0], bh1c = sPC[768+j1];

    const u32 bRd0 = smb + OFF_H + (u32)nrow * 256;    // parity 0
    const u32 bRd1 = bRd0 + 4096;                      // parity 1

    // per-sp chunk-select offsets: lane group bg fetches chunk 4*sp+bg
    u32 cbo[4];
    #pragma unroll
    for (int sp = 0; sp < 4; sp++)
        cbo[sp] = (u32)((((4 * sp + bg) ^ nrow) & 15) << 4);

    // lane's h elements: [0]=(j0,c0) [1]=(j0,c1) [2]=(j1,c0) [3]=(j1,c1)
    float hreg[4] = {0.f, 0.f, 0.f, 0.f};

    for (int t = 0; t < TT; t++) {
        const int p = t & 1;
        const u32 bRd = p ? bRd1 : bRd0;
        char* hw = sm + OFF_H + (p ^ 1) * 4096;

        // ==== MMA: r,z,n = Whi * h_q (1-term fp16, fp32 accumulate) ====
        float accr[4] = {0.f,0.f,0.f,0.f};
        float accz[4] = {0.f,0.f,0.f,0.f};
        float accn[4] = {0.f,0.f,0.f,0.f};
        u32 bq[2][4];
        ldsm4(bq[0][0], bq[0][1], bq[0][2], bq[0][3], bRd + cbo[0]);
        #pragma unroll
        for (int sp = 0; sp < 4; sp++) {
            const int cu = sp & 1, nx = cu ^ 1;
            if (sp < 3) ldsm4(bq[nx][0], bq[nx][1], bq[nx][2], bq[nx][3], bRd + cbo[sp + 1]);
            const int s0 = 2 * sp, s1 = 2 * sp + 1;
            mma16816(accr, ar_h[s0], bq[cu][0], bq[cu][1]);
            mma16816(accz, az_h[s0], bq[cu][0], bq[cu][1]);
            mma16816(accn, an_h[s0], bq[cu][0], bq[cu][1]);
            mma16816(accr, ar_h[s1], bq[cu][2], bq[cu][3]);
            mma16816(accz, az_h[s1], bq[cu][2], bq[cu][3]);
            mma16816(accn, an_h[s1], bq[cu][2], bq[cu][3]);
        }

        // ============ gates + state update, fully in-register ============
        const float xv0 = sXf[c0 * TT + t];
        const float xv1 = sXf[c1 * TT + t];
        #pragma unroll
        for (int i = 0; i < 4; i++) {
            const int jj = i >> 1;                 // 0 -> j0 consts, 1 -> j1
            const float xv = (i & 1) ? xv1 : xv0;
            const float wr = jj ? wr1 : wr0, wz = jj ? wz1 : wz0, wn = jj ? wn1 : wn0;
            const float br = jj ? br1 : br0, bz = jj ? bz1 : bz0;
            const float bi = jj ? bi1 : bi0, bh_ = jj ? bh1c : bh0c;
            float rg = sigm_(fmaf(xv, wr, br) + accr[i]);
            float zg = sigm_(fmaf(xv, wz, bz) + accz[i]);
            float ng = tanha_(fmaf(xv, wn, bi) + rg * (accn[i] + bh_));
            float hn = fmaf(zg, hreg[i] - ng, ng);          // (1-z)*n + z*h
            hreg[i] = hn;
            const int jx = jj ? j1 : j0;
            const int bx = (i & 1) ? c1 : c0;
            *(__half*)(hw + swz(bx, jx)) = __float2half_rn(hn);
        }
        __syncthreads();
    }

    // ============ epilogue: concat[b][v] ============
    float* hfin = (float*)(sm + OFF_X);   // reuse x region: [8][128] f32
    hfin[c0 * HH + j0] = hreg[0];
    hfin[c1 * HH + j0] = hreg[1];
    hfin[c0 * HH + j1] = hreg[2];
    hfin[c1 * HH + j1] = hreg[3];
    __syncthreads();

    {
        const float* Wp_v = Wp + v * HH;
        float s = 0.0f;
        #pragma unroll
        for (int q = 0; q < 4; q++) {
            int jj = L + 32 * q;
            s = fmaf(hfin[w * HH + jj], Wp_v[jj], s);
        }
        #pragma unroll
        for (int off = 16; off; off >>= 1) s += __shfl_xor_sync(0xffffffffu, s, off);
        if (L == 0) g_concat[(b0g + w) * VV + v] = s + bp[v];
    }
}

// one CTA per batch row; warp-per-class output reduction
__global__ __launch_bounds__(256, 1)
void fc_kernel(const float* __restrict__ W1, const float* __restrict__ b1,
               const float* __restrict__ W2, const float* __restrict__ b2,
               float* __restrict__ out)
{
    __shared__ float sC[VV];
    __shared__ float sF[FCN];

    const int b = blockIdx.x;
    const int tid = threadIdx.x;

    if (tid < VV) sC[tid] = g_concat[b * VV + tid];
    __syncthreads();

    {
        float a = b1[tid];
        const float* w1 = W1 + tid * VV;
        #pragma unroll
        for (int vv = 0; vv < VV; vv++) a = fmaf(sC[vv], w1[vv], a);
        sF[tid] = fmaxf(a, 0.0f);
    }
    __syncthreads();

    const int wid = tid >> 5, lane = tid & 31;
    for (int c = wid; c < CC; c += 8) {
        const float* w2 = W2 + c * FCN;
        float a = 0.0f;
        #pragma unroll
        for (int q = 0; q < FCN / 32; q++) {
            int f = lane + 32 * q;
            a = fmaf(sF[f], w2[f], a);
        }
        #pragma unroll
        for (int off = 16; off; off >>= 1) a += __shfl_xor_sync(0xffffffffu, a, off);
        if (lane == 0) out[b * CC + c] = a + b2[c];
    }
}

extern "C" void kernel_launch(void* const* d_in, const int* in_sizes, int n_in,
                              void* d_out, int out_size)
{
    const float* x   = (const float*)d_in[0];
    const float* Wih = (const float*)d_in[1];
    const float* Whh = (const float*)d_in[2];
    const float* bih = (const float*)d_in[3];
    const float* bhh = (const float*)d_in[4];
    const float* Wp  = (const float*)d_in[5];
    const float* bp  = (const float*)d_in[6];
    const float* W1  = (const float*)d_in[7];
    const float* b1  = (const float*)d_in[8];
    const float* W2  = (const float*)d_in[9];
    const float* b2  = (const float*)d_in[10];
    float* out = (float*)d_out;

    cudaFuncSetAttribute(gru_kernel, cudaFuncAttributeMaxDynamicSharedMemorySize, SMEM_TOT);
    gru_kernel<<<VV * (BB / NB), NTHR, SMEM_TOT>>>(x, Wih, Whh, bih, bhh, Wp, bp);
    fc_kernel<<<BB, 256>>>(W1, b1, W2, b2, out);
}

// round 13
// speedup vs baseline: 8.6243x; 1.0164x over previous
#include <cuda_runtime.h>
#include <cuda_fp16.h>
#include <math.h>

#define VV 16
#define BB 64
#define TT 256
#define HH 128
#define GG 384
#define FCN 256
#define CC 10
#define NB 8            // batch rows per CTA = MMA N
#define NTHR 256        // 8 warps; warp w owns j-range [16w, 16w+16) for ALL 3 gates
#define NCTA 128

// ---- smem byte offsets ----
#define OFF_WHI 0                        // W_hi fp16 [384][128] swizzled (reused as const table)
#define OFF_H   (OFF_WHI + GG*256)       // 98304: h_q fp16 tiles, 2 parity bufs x 4KB
#define OFF_X   (OFF_H + 2*4096)         // 106496: x f32 [8][256] (reused as hfin / fc scratch)
#define SMEM_TOT (OFF_X + NB*TT*4)       // 114688

typedef unsigned int u32;

__device__ float g_concat[BB * VV];
__device__ int g_ctr = 0;
__device__ int g_ctr2 = 0;

// XOR-swizzled byte offset within a [rows][128] 16-bit tile (256B rows, 16B chunks)
__device__ __forceinline__ int swz(int r, int k) {
    return r * 256 + ((((k >> 3) ^ (r & 7)) & 15) << 4) + ((k & 7) << 1);
}

__device__ __forceinline__ u32 smem_u32(const void* p) {
    u32 a;
    asm("{ .reg .u64 t; cvta.to.shared.u64 t, %1; cvt.u32.u64 %0, t; }" : "=r"(a) : "l"(p));
    return a;
}

__device__ __forceinline__ void ldsm4(u32& a0, u32& a1, u32& a2, u32& a3, u32 addr) {
    asm volatile("ldmatrix.sync.aligned.m8n8.x4.shared.b16 {%0,%1,%2,%3}, [%4];"
                 : "=r"(a0), "=r"(a1), "=r"(a2), "=r"(a3) : "r"(addr));
}
__device__ __forceinline__ void mma16816(float* d, const u32* a, u32 b0, u32 b1) {
    asm volatile("mma.sync.aligned.m16n8k16.row.col.f32.f16.f16.f32 "
                 "{%0,%1,%2,%3}, {%4,%5,%6,%7}, {%8,%9}, {%0,%1,%2,%3};"
                 : "+f"(d[0]), "+f"(d[1]), "+f"(d[2]), "+f"(d[3])
                 : "r"(a[0]), "r"(a[1]), "r"(a[2]), "r"(a[3]), "r"(b0), "r"(b1));
}

__device__ __forceinline__ float tanha_(float x) {
    float y;
    asm("tanh.approx.f32 %0, %1;" : "=f"(y) : "f"(x));
    return y;
}
__device__ __forceinline__ float sigm_(float x) {
    return fmaf(0.5f, tanha_(0.5f * x), 0.5f);
}

__global__ __launch_bounds__(NTHR, 1)
void gru_kernel(const float* __restrict__ x,   const float* __restrict__ Wih,
                const float* __restrict__ Whh, const float* __restrict__ bih,
                const float* __restrict__ bhh, const float* __restrict__ Wp,
                const float* __restrict__ bp,  const float* __restrict__ W1,
                const float* __restrict__ b1,  const float* __restrict__ W2,
                const float* __restrict__ b2,  float* __restrict__ out)
{
    extern __shared__ char sm[];
    const u32 smb = smem_u32(sm);
    const int tid = threadIdx.x;
    const int v  = blockIdx.x >> 3;          // 16 variables
    const int b0g = (blockIdx.x & 7) * NB;   // 8 batch-groups of 8

    // ---- stage Whh[v] as fp16 into swizzled tile ----
    const float* Whh_v = Whh + (size_t)v * GG * HH;
    for (int idx = tid; idx < GG * HH; idx += NTHR) {
        int g = idx >> 7, k = idx & 127;
        *(__half*)(sm + OFF_WHI + swz(g, k)) = __float2half_rn(Whh_v[idx]);
    }
    // ---- zero h parity-buffer 0; buffer 1 fully written at t=0 ----
    for (int idx = tid; idx < 4096 / 4; idx += NTHR)
        ((u32*)(sm + OFF_H))[idx] = 0u;
    // ---- stage x slice ----
    float* sXf = (float*)(sm + OFF_X);
    const float* x_v = x + (size_t)(v * BB + b0g) * TT;
    for (int idx = tid; idx < NB * TT; idx += NTHR) sXf[idx] = x_v[idx];

    // ---- lane geometry ----
    const int w = tid >> 5, L = tid & 31;
    const int rowl  = ((L >> 3) & 1) * 8 + (L & 7);  // A frag row within 16-tile
    const int khalf = (L >> 4) & 1;
    const int xr    = L & 7;
    const int nrow = L & 7;
    const int bg   = (L >> 3) & 3;
    const int quad = L >> 2, qc = L & 3;
    const int j0 = 16 * w + quad, j1 = j0 + 8;       // this lane's j rows
    const int c0 = 2 * qc, c1 = 2 * qc + 1;          // this lane's b cols

    __syncthreads();

    // ---- preload A fragments: all 3 gates, W_hi only (1-term fp16) ----
    u32 ar_h[8][4], az_h[8][4], an_h[8][4];
    {
        const u32 aR = smb + OFF_WHI + (u32)(16 * w + rowl) * 256;           // gate r
        const u32 aZ = aR + 128 * 256;                                        // gate z
        const u32 aN = aR + 256 * 256;                                        // gate n
        #pragma unroll
        for (int s = 0; s < 8; s++) {
            const u32 ca = (u32)((((2 * s + khalf) ^ xr) & 15) << 4);
            ldsm4(ar_h[s][0], ar_h[s][1], ar_h[s][2], ar_h[s][3], aR + ca);
            ldsm4(az_h[s][0], az_h[s][1], az_h[s][2], az_h[s][3], aZ + ca);
            ldsm4(an_h[s][0], an_h[s][1], an_h[s][2], an_h[s][3], aN + ca);
        }
    }
    __syncthreads();

    // ---- gate constants (register-resident, 2 j values) via smem bounce ----
    float* sPC = (float*)(sm + OFF_WHI);   // reuse dead W region
    if (tid < 128) {
        sPC[tid]       = Wih[v * GG + tid];
        sPC[128 + tid] = Wih[v * GG + 128 + tid];
        sPC[256 + tid] = Wih[v * GG + 256 + tid];
        sPC[384 + tid] = bih[v * GG + tid]       + bhh[v * GG + tid];
        sPC[512 + tid] = bih[v * GG + 128 + tid] + bhh[v * GG + 128 + tid];
        sPC[640 + tid] = bih[v * GG + 256 + tid];
        sPC[768 + tid] = bhh[v * GG + 256 + tid];
    }
    __syncthreads();
    const float wr0 = sPC[j0],      wr1 = sPC[j1];
    const float wz0 = sPC[128+j0],  wz1 = sPC[128+j1];
    const float wn0 = sPC[256+j0],  wn1 = sPC[256+j1];
    const float br0 = sPC[384+j0],  br1 = sPC[384+j1];
    const float bz0 = sPC[512+j0],  bz1 = sPC[512+j1];
    const float bi0 = sPC[640+j0],  bi1 = sPC[640+j1];
    const float bh0c = sPC[768+j0], bh1c = sPC[768+j1];

    const u32 bRd0 = smb + OFF_H + (u32)nrow * 256;    // parity 0
    const u32 bRd1 = bRd0 + 4096;                      // parity 1

    // per-sp chunk-select offsets: lane group bg fetches chunk 4*sp+bg
    u32 cbo[4];
    #pragma unroll
    for (int sp = 0; sp < 4; sp++)
        cbo[sp] = (u32)((((4 * sp + bg) ^ nrow) & 15) << 4);

    // lane's h elements: [0]=(j0,c0) [1]=(j0,c1) [2]=(j1,c0) [3]=(j1,c1)
    float hreg[4] = {0.f, 0.f, 0.f, 0.f};

    for (int t = 0; t < TT; t++) {
        const int p = t & 1;
        const u32 bRd = p ? bRd1 : bRd0;
        char* hw = sm + OFF_H + (p ^ 1) * 4096;

        // ---- hoisted i-gates (depend only on x): overlap their latency with MMA ----
        const float xv0 = sXf[c0 * TT + t];
        const float xv1 = sXf[c1 * TT + t];
        float irv[4], izv[4], inv[4];
        #pragma unroll
        for (int i = 0; i < 4; i++) {
            const int jj = i >> 1;
            const float xv = (i & 1) ? xv1 : xv0;
            irv[i] = fmaf(xv, jj ? wr1 : wr0, jj ? br1 : br0);
            izv[i] = fmaf(xv, jj ? wz1 : wz0, jj ? bz1 : bz0);
            inv[i] = fmaf(xv, jj ? wn1 : wn0, jj ? bi1 : bi0);
        }

        // ==== MMA: r,z,n = Whi * h_q ; split accumulators (even/odd s) ====
        float accrA[4] = {0.f,0.f,0.f,0.f}, accrB[4] = {0.f,0.f,0.f,0.f};
        float acczA[4] = {0.f,0.f,0.f,0.f}, acczB[4] = {0.f,0.f,0.f,0.f};
        float accnA[4] = {0.f,0.f,0.f,0.f}, accnB[4] = {0.f,0.f,0.f,0.f};
        u32 bq[2][4];
        ldsm4(bq[0][0], bq[0][1], bq[0][2], bq[0][3], bRd + cbo[0]);
        #pragma unroll
        for (int sp = 0; sp < 4; sp++) {
            const int cu = sp & 1, nx = cu ^ 1;
            if (sp < 3) ldsm4(bq[nx][0], bq[nx][1], bq[nx][2], bq[nx][3], bRd + cbo[sp + 1]);
            const int s0 = 2 * sp, s1 = 2 * sp + 1;
            mma16816(accrA, ar_h[s0], bq[cu][0], bq[cu][1]);
            mma16816(acczA, az_h[s0], bq[cu][0], bq[cu][1]);
            mma16816(accnA, an_h[s0], bq[cu][0], bq[cu][1]);
            mma16816(accrB, ar_h[s1], bq[cu][2], bq[cu][3]);
            mma16816(acczB, az_h[s1], bq[cu][2], bq[cu][3]);
            mma16816(accnB, an_h[s1], bq[cu][2], bq[cu][3]);
        }

        // ============ gates + state update, fully in-register ============
        #pragma unroll
        for (int i = 0; i < 4; i++) {
            const int jj = i >> 1;
            const float bh_ = jj ? bh1c : bh0c;
            float rg = sigm_(irv[i] + (accrA[i] + accrB[i]));
            float zg = sigm_(izv[i] + (acczA[i] + acczB[i]));
            float ng = tanha_(inv[i] + rg * ((accnA[i] + accnB[i]) + bh_));
            float hn = fmaf(zg, hreg[i] - ng, ng);          // (1-z)*n + z*h
            hreg[i] = hn;
            const int jx = jj ? j1 : j0;
            const int bx = (i & 1) ? c1 : c0;
            *(__half*)(hw + swz(bx, jx)) = __float2half_rn(hn);
        }
        __syncthreads();
    }

    // ============ epilogue: concat[b][v] ============
    float* hfin = (float*)(sm + OFF_X);   // reuse x region: [8][128] f32
    hfin[c0 * HH + j0] = hreg[0];
    hfin[c1 * HH + j0] = hreg[1];
    hfin[c0 * HH + j1] = hreg[2];
    hfin[c1 * HH + j1] = hreg[3];
    __syncthreads();

    {
        const float* Wp_v = Wp + v * HH;
        float s = 0.0f;
        #pragma unroll
        for (int q = 0; q < 4; q++) {
            int jj = L + 32 * q;
            s = fmaf(hfin[w * HH + jj], Wp_v[jj], s);
        }
        #pragma unroll
        for (int off = 16; off; off >>= 1) s += __shfl_xor_sync(0xffffffffu, s, off);
        if (L == 0) g_concat[(b0g + w) * VV + v] = s + bp[v];
    }

    // ============ fused classifier (was fc_kernel) ============
    // publish this CTA's concat rows, then CTAs 0..63 each handle one batch row.
    __syncthreads();
    if (tid == 0) {
        __threadfence();
        atomicAdd(&g_ctr, 1);
    }
    if (blockIdx.x < BB) {
        const int b = blockIdx.x;
        if (tid == 0) {
            while (atomicAdd(&g_ctr, 0) < NCTA) {}
            __threadfence();
        }
        __syncthreads();

        float* sC = (float*)(sm + OFF_X);          // VV floats
        float* sF = (float*)(sm + OFF_X + 256);    // FCN floats
        if (tid < VV) sC[tid] = g_concat[b * VV + tid];
        __syncthreads();

        {
            float a = b1[tid];
            const float* w1 = W1 + tid * VV;
            #pragma unroll
            for (int vv = 0; vv < VV; vv++) a = fmaf(sC[vv], w1[vv], a);
            sF[tid] = fmaxf(a, 0.0f);
        }
        __syncthreads();

        for (int c = w; c < CC; c += 8) {
            const float* w2 = W2 + c * FCN;
            float a = 0.0f;
            #pragma unroll
            for (int q = 0; q < FCN / 32; q++) {
                int f = L + 32 * q;
                a = fmaf(sF[f], w2[f], a);
            }
            #pragma unroll
            for (int off = 16; off; off >>= 1) a += __shfl_xor_sync(0xffffffffu, a, off);
            if (L == 0) out[b * CC + c] = a + b2[c];
        }
        __syncthreads();
        if (tid == 0) {
            int t2 = atomicAdd(&g_ctr2, 1);
            if (t2 == BB - 1) { g_ctr = 0; g_ctr2 = 0; __threadfence(); }
        }
    }
}

extern "C" void kernel_launch(void* const* d_in, const int* in_sizes, int n_in,
                              void* d_out, int out_size)
{
    const float* x   = (const float*)d_in[0];
    const float* Wih = (const float*)d_in[1];
    const float* Whh = (const float*)d_in[2];
    const float* bih = (const float*)d_in[3];
    const float* bhh = (const float*)d_in[4];
    const float* Wp  = (const float*)d_in[5];
    const float* bp  = (const float*)d_in[6];
    const float* W1  = (const float*)d_in[7];
    const float* b1  = (const float*)d_in[8];
    const float* W2  = (const float*)d_in[9];
    const float* b2  = (const float*)d_in[10];
    float* out = (float*)d_out;

    cudaFuncSetAttribute(gru_kernel, cudaFuncAttributeMaxDynamicSharedMemorySize, SMEM_TOT);
    gru_kernel<<<NCTA, NTHR, SMEM_TOT>>>(x, Wih, Whh, bih, bhh, Wp, bp,
                                         W1, b1, W2, b2, out);
}